// round 14
// baseline (speedup 1.0000x reference)
#include <cuda_runtime.h>
#include <cuda_fp16.h>
#include <cstdint>

// Problem constants
#define Nn 50000
#define Hh 512
#define Dd 256
#define Ee 200000
#define Pp 100000
#define KS 2048   // 4*H stacked K dimension
#define AGGW 1536 // 3*H agg row width

// rgcn mma tile config (KC=64)
#define MT 128
#define NTT 128
#define KC64 64
#define CH64 (KS / KC64)    // 32
// stage layout: rows have 144B pitch (64 fp16 + 8 pad)
#define APITCH 144
#define BH_OFF 18432
#define BL_OFF 36864
#define STAGE64 55296
#define SMEM_TC (2 * STAGE64)   // 108KB -> 2 CTAs/SM

// scoring mma config (KC=32, in-register A path)
#define KC 32
#define SCH (768 / KC)      // 24
#define A_HI 0
#define B_HI 10240
#define B_LO 20480
#define STAGE 30720
#define SMEM_SC (2 * STAGE)

// CSR scan config
#define SCB 256
#define SCNB ((Nn + SCB - 1) / SCB)

// ---------------- scratch (device globals; no allocation) ----------------
__device__ float g_x2[(size_t)Nn * Hh];   // fp32 layer-1 out (residual base)
__device__ float g_h [(size_t)Nn * Hh];
__device__ float g_z [(size_t)Nn * Dd];
__device__ __align__(16) __half g_xb0[(size_t)Nn * Hh];
__device__ __align__(16) __half g_xb1[(size_t)Nn * Hh];
__device__ __align__(16) __half g_agg[(size_t)Nn * AGGW];
// per-layer weight buffers (hi/lo fp16, [HO][K])
__device__ __align__(16) __half g_wt1h[(size_t)512 * KS];
__device__ __align__(16) __half g_wt1l[(size_t)512 * KS];
__device__ __align__(16) __half g_wt2h[(size_t)512 * KS];
__device__ __align__(16) __half g_wt2l[(size_t)512 * KS];
__device__ __align__(16) __half g_wt3h[(size_t)256 * KS];
__device__ __align__(16) __half g_wt3l[(size_t)256 * KS];
__device__ __align__(16) __half g_wtsh[(size_t)256 * 768];
__device__ __align__(16) __half g_wtsl[(size_t)256 * 768];
// CSR
__device__ int g_deg  [3 * Nn];
__device__ int g_start[3 * Nn];
__device__ int g_cur  [3 * Nn];
__device__ int g_part [3 * SCNB];
__device__ int g_csr  [3 * (size_t)Ee];

// ======================= PTX helpers =======================
__device__ __forceinline__ uint32_t smem_u32(const void* p) {
    uint32_t a;
    asm("{ .reg .u64 t; cvta.to.shared.u64 t, %1; cvt.u32.u64 %0, t; }" : "=r"(a) : "l"(p));
    return a;
}
#define STS64(addr, val) \
    asm volatile("st.shared.b64 [%0], %1;" :: "r"(addr), "l"(val) : "memory")
#define CP16(dst, src) \
    asm volatile("cp.async.cg.shared.global [%0], [%1], 16;" :: "r"(dst), "l"(src) : "memory")
#define CPCOMMIT() asm volatile("cp.async.commit_group;" ::: "memory")
#define CPWAIT(n)  asm volatile("cp.async.wait_group %0;" :: "n"(n) : "memory")
#define LDSM_X4(r0, r1, r2, r3, addr) \
    asm volatile("ldmatrix.sync.aligned.m8n8.x4.shared.b16 {%0,%1,%2,%3},[%4];" \
                 : "=r"(r0), "=r"(r1), "=r"(r2), "=r"(r3) : "r"(addr))
#define MMA16816(d, a, b) \
    asm volatile("mma.sync.aligned.m16n8k16.row.col.f32.f16.f16.f32 " \
                 "{%0,%1,%2,%3},{%4,%5,%6,%7},{%8,%9},{%0,%1,%2,%3};" \
                 : "+f"((d)[0]), "+f"((d)[1]), "+f"((d)[2]), "+f"((d)[3]) \
                 : "r"((a)[0]), "r"((a)[1]), "r"((a)[2]), "r"((a)[3]), \
                   "r"((b)[0]), "r"((b)[1]))

// fp32 -> fp16 hi/lo split (weights)
__device__ __forceinline__ void split1h(float v, __half& h, __half& l) {
    h = __float2half(v);
    l = __float2half(v - __half2float(h));
}
__device__ __forceinline__ void pack4_store(__half* hp, float4 v) {
    __half2 h0 = __floats2half2_rn(v.x, v.y);
    __half2 h1 = __floats2half2_rn(v.z, v.w);
    uint2 u;
    u.x = *reinterpret_cast<uint32_t*>(&h0);
    u.y = *reinterpret_cast<uint32_t*>(&h1);
    *reinterpret_cast<uint2*>(hp) = u;
}
__device__ __forceinline__ void cvt_sts(uint32_t addr, float4 v) {
    __half2 h0 = __floats2half2_rn(v.x, v.y);
    __half2 h1 = __floats2half2_rn(v.z, v.w);
    uint32_t u0 = *reinterpret_cast<uint32_t*>(&h0);
    uint32_t u1 = *reinterpret_cast<uint32_t*>(&h1);
    STS64(addr, ((uint64_t)u1 << 32) | u0);
}
__device__ __forceinline__ void acc_h4(float4& acc, uint2 u) {
    __half2 a = *reinterpret_cast<__half2*>(&u.x);
    __half2 b = *reinterpret_cast<__half2*>(&u.y);
    float2 fa = __half22float2(a);
    float2 fb = __half22float2(b);
    acc.x += fa.x; acc.y += fa.y; acc.z += fb.x; acc.w += fb.y;
}

// KC=64 chunk of fp16 2-pass mma (144B pitch)
__device__ __forceinline__ void mma_chunk64(uint32_t base, int wm, int wn, int lane,
                                            float acc[4][4][4]) {
#pragma unroll
    for (int ksf = 0; ksf < 4; ksf++) {
        uint32_t a_addr = base +
                          (uint32_t)(wm * 64 + (lane & 15)) * APITCH +
                          (uint32_t)(ksf * 16 + (lane >> 4) * 8) * 2u;
        uint32_t ah[4][4];
#pragma unroll
        for (int i = 0; i < 4; i++)
            LDSM_X4(ah[i][0], ah[i][1], ah[i][2], ah[i][3], a_addr + i * 16 * APITCH);
        int g = lane >> 3;
        uint32_t b_n = (uint32_t)(wn * 32 + ((g >> 1) << 3) + (lane & 7));
        uint32_t b_k = (uint32_t)(ksf * 16 + ((g & 1) << 3));
        uint32_t b_addr = base + BH_OFF + b_n * APITCH + b_k * 2u;
        uint32_t bh[4][2], bl[4][2];
#pragma unroll
        for (int jp = 0; jp < 2; jp++) {
            LDSM_X4(bh[2 * jp][0], bh[2 * jp][1], bh[2 * jp + 1][0], bh[2 * jp + 1][1],
                    b_addr + jp * 16 * APITCH);
            LDSM_X4(bl[2 * jp][0], bl[2 * jp][1], bl[2 * jp + 1][0], bl[2 * jp + 1][1],
                    b_addr + (BL_OFF - BH_OFF) + jp * 16 * APITCH);
        }
#pragma unroll
        for (int i = 0; i < 4; i++)
#pragma unroll
            for (int j = 0; j < 4; j++) {
                MMA16816(acc[i][j], ah[i], bh[j]);
                MMA16816(acc[i][j], ah[i], bl[j]);
            }
    }
}

// KC=32 chunk (80B pitch) for scoring
__device__ __forceinline__ void mma_chunk32(uint32_t base, int wm, int wn, int lane,
                                            float acc[4][4][4]) {
#pragma unroll
    for (int ksf = 0; ksf < 2; ksf++) {
        uint32_t a_addr = base + A_HI +
                          (uint32_t)(wm * 64 + (lane & 15)) * 80u +
                          (uint32_t)(ksf * 16 + (lane >> 4) * 8) * 2u;
        uint32_t ah[4][4];
#pragma unroll
        for (int i = 0; i < 4; i++)
            LDSM_X4(ah[i][0], ah[i][1], ah[i][2], ah[i][3], a_addr + i * 16 * 80);
        int g = lane >> 3;
        uint32_t b_n = (uint32_t)(wn * 32 + ((g >> 1) << 3) + (lane & 7));
        uint32_t b_k = (uint32_t)(ksf * 16 + ((g & 1) << 3));
        uint32_t b_addr = base + B_HI + b_n * 80u + b_k * 2u;
        uint32_t bh[4][2], bl[4][2];
#pragma unroll
        for (int jp = 0; jp < 2; jp++) {
            LDSM_X4(bh[2 * jp][0], bh[2 * jp][1], bh[2 * jp + 1][0], bh[2 * jp + 1][1],
                    b_addr + jp * 16 * 80);
            LDSM_X4(bl[2 * jp][0], bl[2 * jp][1], bl[2 * jp + 1][0], bl[2 * jp + 1][1],
                    b_addr + 10240u + jp * 16 * 80);
        }
#pragma unroll
        for (int i = 0; i < 4; i++)
#pragma unroll
            for (int j = 0; j < 4; j++) {
                MMA16816(acc[i][j], ah[i], bh[j]);
                MMA16816(acc[i][j], ah[i], bl[j]);
            }
    }
}

// ---------------- encode: xb0 fp16 ----------------
__global__ void encode_k(const int* __restrict__ types,
                         const float* __restrict__ node_emb,
                         const float* __restrict__ type_emb) {
    int i = blockIdx.x * blockDim.x + threadIdx.x;
    if (i >= Nn * (Hh / 4)) return;
    int n = i >> 7;
    int q = i & 127;
    float4 a = ((const float4*)node_emb)[i];
    float4 b = ((const float4*)type_emb)[(size_t)types[n] * 128 + q];
    a.x += b.x; a.y += b.y; a.z += b.z; a.w += b.w;
    pack4_store(g_xb0 + (size_t)n * Hh + q * 4, a);
}

// ---------------- CSR build ----------------
__global__ void csr_zero_k() {
    int i = blockIdx.x * blockDim.x + threadIdx.x;
    if (i < 3 * Nn) { g_deg[i] = 0; g_cur[i] = 0; }
}
__global__ void csr_count_k(const int* __restrict__ d0, const int* __restrict__ d1,
                            const int* __restrict__ d2) {
    int e = blockIdx.x * blockDim.x + threadIdx.x;
    if (e >= Ee) return;
    atomicAdd(&g_deg[0 * Nn + d0[e]], 1);
    atomicAdd(&g_deg[1 * Nn + d1[e]], 1);
    atomicAdd(&g_deg[2 * Nn + d2[e]], 1);
}
__global__ void csr_scan1_k() {
    __shared__ int sm[SCB];
    int r = blockIdx.y;
    int i = blockIdx.x * SCB + threadIdx.x;
    sm[threadIdx.x] = (i < Nn) ? g_deg[r * Nn + i] : 0;
    __syncthreads();
    for (int o = SCB / 2; o; o >>= 1) {
        if (threadIdx.x < o) sm[threadIdx.x] += sm[threadIdx.x + o];
        __syncthreads();
    }
    if (threadIdx.x == 0) g_part[r * SCNB + blockIdx.x] = sm[0];
}
__global__ void csr_scan2_k() {
    __shared__ int sm[SCB];
    int r = blockIdx.x;
    int t = threadIdx.x;
    int v = (t < SCNB) ? g_part[r * SCNB + t] : 0;
    sm[t] = v;
    __syncthreads();
    for (int o = 1; o < SCB; o <<= 1) {
        int u = (t >= o) ? sm[t - o] : 0;
        __syncthreads();
        sm[t] += u;
        __syncthreads();
    }
    if (t < SCNB) g_part[r * SCNB + t] = sm[t] - v;
}
__global__ void csr_scan3_k() {
    __shared__ int sm[SCB];
    int r = blockIdx.y;
    int i = blockIdx.x * SCB + threadIdx.x;
    int v = (i < Nn) ? g_deg[r * Nn + i] : 0;
    sm[threadIdx.x] = v;
    __syncthreads();
    for (int o = 1; o < SCB; o <<= 1) {
        int t = (threadIdx.x >= o) ? sm[threadIdx.x - o] : 0;
        __syncthreads();
        sm[threadIdx.x] += t;
        __syncthreads();
    }
    if (i < Nn)
        g_start[r * Nn + i] = g_part[r * SCNB + blockIdx.x] + sm[threadIdx.x] - v;
}
__global__ void csr_fill_k(const int* __restrict__ s0, const int* __restrict__ d0,
                           const int* __restrict__ s1, const int* __restrict__ d1,
                           const int* __restrict__ s2, const int* __restrict__ d2) {
    int e = blockIdx.x * blockDim.x + threadIdx.x;
    if (e >= Ee) return;
    {
        int d = d0[e];
        int p = atomicAdd(&g_cur[0 * Nn + d], 1);
        g_csr[(size_t)0 * Ee + g_start[0 * Nn + d] + p] = s0[e];
    }
    {
        int d = d1[e];
        int p = atomicAdd(&g_cur[1 * Nn + d], 1);
        g_csr[(size_t)1 * Ee + g_start[1 * Nn + d] + p] = s1[e];
    }
    {
        int d = d2[e];
        int p = atomicAdd(&g_cur[2 * Nn + d], 1);
        g_csr[(size_t)2 * Ee + g_start[2 * Nn + d] + p] = s2[e];
    }
}

// ---------------- gather aggregation (fp16 in/out, no smem, all 3 relations) ----------------
__global__ void agg_k(const __half* __restrict__ xin) {
    const int n = blockIdx.x;
    const int t = threadIdx.x;   // 128; thread covers cols 4t..4t+3
    for (int r = 0; r < 3; r++) {
        const int s = g_start[r * Nn + n];
        const int d = g_deg[r * Nn + n];
        const int* lst = g_csr + (size_t)r * Ee + s;
        float4 acc = make_float4(0.f, 0.f, 0.f, 0.f);
        int i = 0;
        for (; i + 4 <= d; i += 4) {
            int s0 = lst[i + 0], s1 = lst[i + 1], s2 = lst[i + 2], s3 = lst[i + 3];
            uint2 u0 = ((const uint2*)(xin + (size_t)s0 * Hh))[t];
            uint2 u1 = ((const uint2*)(xin + (size_t)s1 * Hh))[t];
            uint2 u2 = ((const uint2*)(xin + (size_t)s2 * Hh))[t];
            uint2 u3 = ((const uint2*)(xin + (size_t)s3 * Hh))[t];
            acc_h4(acc, u0); acc_h4(acc, u1); acc_h4(acc, u2); acc_h4(acc, u3);
        }
        for (; i < d; i++) {
            uint2 u = ((const uint2*)(xin + (size_t)lst[i] * Hh))[t];
            acc_h4(acc, u);
        }
        pack4_store(g_agg + (size_t)n * AGGW + r * Hh + t * 4, acc);
    }
}

// ---------------- weight transpose + fp16 hi/lo split (tiled, coalesced) ----------------
__global__ void wt_build_k(const float* __restrict__ wl,
                           const float* __restrict__ wr, int HO,
                           __half* __restrict__ outh, __half* __restrict__ outl) {
    __shared__ float tile[32][33];
    int k0 = blockIdx.x * 32;
    int n0 = blockIdx.y * 32;
    int tx = threadIdx.x & 31, ty = threadIdx.x >> 5;
#pragma unroll
    for (int i = 0; i < 4; i++) {
        int k = k0 + ty + i * 8;
        int n = n0 + tx;
        float v = (k < Hh) ? wl[(size_t)k * HO + n] : wr[(size_t)(k - Hh) * HO + n];
        tile[ty + i * 8][tx] = v;
    }
    __syncthreads();
#pragma unroll
    for (int i = 0; i < 4; i++) {
        int n = n0 + ty + i * 8;
        int k = k0 + tx;
        float v = tile[tx][ty + i * 8];
        __half h, l;
        split1h(v, h, l);
        outh[(size_t)n * KS + k] = h;
        outl[(size_t)n * KS + k] = l;
    }
}
__global__ void wt_build_score_k(const float* __restrict__ w1) {
    __shared__ float tile[32][33];
    int k0 = blockIdx.x * 32;
    int n0 = blockIdx.y * 32;
    int tx = threadIdx.x & 31, ty = threadIdx.x >> 5;
#pragma unroll
    for (int i = 0; i < 4; i++) {
        int k = k0 + ty + i * 8;
        tile[ty + i * 8][tx] = w1[(size_t)k * 256 + n0 + tx];
    }
    __syncthreads();
#pragma unroll
    for (int i = 0; i < 4; i++) {
        int n = n0 + ty + i * 8;
        int k = k0 + tx;
        float v = tile[tx][ty + i * 8];
        __half h, l;
        split1h(v, h, l);
        g_wtsh[(size_t)n * 768 + k] = h;
        g_wtsl[(size_t)n * 768 + k] = l;
    }
}

// ---------------- RGCN GEMM (KC=64, 2-stage, 1 sync/chunk) ----------------
template <int HO, int MODE>
__global__ void __launch_bounds__(256, 2) rgcn_mma_k(
    const __half* __restrict__ xh,
    const __half* __restrict__ wth, const __half* __restrict__ wtl,
    float* __restrict__ outf,
    __half* __restrict__ oh) {
    extern __shared__ char sm_[];
    const uint32_t sb = smem_u32(sm_);
    const int tid = threadIdx.x;
    const int wid = tid >> 5, lane = tid & 31;
    const int wm = wid & 1, wn = wid >> 1;
    const int m0 = blockIdx.y * MT;
    const int n0 = blockIdx.x * NTT;

    auto load_stage = [&](int c) {
        uint32_t stage = sb + (uint32_t)(c & 1) * STAGE64;
        int colA = c * KC64;
#pragma unroll
        for (int u = 0; u < 4; u++) {
            int idx = tid * 4 + u;
            int row = idx >> 3, q = idx & 7;
            uint32_t d = stage + (uint32_t)row * APITCH + (uint32_t)q * 16u;
            int gr = m0 + row;
            if (gr >= Nn) gr = Nn - 1;
            const __half* ah;
            if (colA < Hh) {
                ah = xh + (size_t)gr * Hh + colA + q * 8;
            } else {
                ah = g_agg + (size_t)gr * AGGW + (colA - Hh) + q * 8;
            }
            CP16(d, ah);
            size_t ob = (size_t)(n0 + row) * KS + colA + q * 8;
            CP16(d + BH_OFF, wth + ob);
            CP16(d + BL_OFF, wtl + ob);
        }
        CPCOMMIT();
    };

    float acc[4][4][4];
#pragma unroll
    for (int i = 0; i < 4; i++)
#pragma unroll
        for (int j = 0; j < 4; j++)
#pragma unroll
            for (int e = 0; e < 4; e++) acc[i][j][e] = 0.f;

    load_stage(0);

    for (int c = 0; c < CH64; c++) {
        CPWAIT(0);
        __syncthreads();
        if (c + 1 < CH64) load_stage(c + 1);
        mma_chunk64(sb + (uint32_t)(c & 1) * STAGE64, wm, wn, lane, acc);
    }

#pragma unroll
    for (int i = 0; i < 4; i++) {
        int mr = m0 + wm * 64 + i * 16 + (lane >> 2);
#pragma unroll
        for (int j = 0; j < 4; j++) {
            int col = n0 + wn * 32 + j * 8 + (lane & 3) * 2;
#pragma unroll
            for (int hh = 0; hh < 2; hh++) {
                int row = mr + hh * 8;
                if (row >= Nn) continue;
                float v0 = acc[i][j][hh * 2 + 0];
                float v1 = acc[i][j][hh * 2 + 1];
                if (MODE == 0) { v0 = fmaxf(v0, 0.f); v1 = fmaxf(v1, 0.f); }
                *(float2*)(outf + (size_t)row * HO + col) = make_float2(v0, v1);
                if (MODE == 0) {
                    __half2 hp = __floats2half2_rn(v0, v1);
                    *(uint32_t*)(oh + (size_t)row * Hh + col) =
                        *reinterpret_cast<uint32_t*>(&hp);
                }
            }
        }
    }
}

// ---------------- zero output ----------------
__global__ void zero_out_k(float* __restrict__ out) {
    int p = blockIdx.x * blockDim.x + threadIdx.x;
    if (p < Pp) out[p] = 0.f;
}

// ---------------- scoring GEMM (gathered A, cvt in-kernel, 2-stage, fused dot) ----------------
__global__ void __launch_bounds__(256, 2) score_mma_k(const int* __restrict__ pairs,
                                                      const float* __restrict__ b1,
                                                      const float* __restrict__ bng,
                                                      const float* __restrict__ bnb,
                                                      const float* __restrict__ bnm,
                                                      const float* __restrict__ bnv,
                                                      const float* __restrict__ w2,
                                                      float* __restrict__ out) {
    extern __shared__ char sm_[];
    const uint32_t sb = smem_u32(sm_);
    const int tid = threadIdx.x;
    const int wid = tid >> 5, lane = tid & 31;
    const int wm = wid & 1, wn = wid >> 1;
    const int m0 = blockIdx.y * MT;
    const int n0 = blockIdx.x * NTT;

    const int ar = tid >> 1;
    const int ac = tid & 1;
    const int p = m0 + ar;
    const bool aok = p < Pp;
    const int spi = aok ? pairs[p] : 0;
    const int dpi = aok ? pairs[Pp + p] : 0;
    const uint32_t asts = (uint32_t)ar * 80u + (uint32_t)ac * 32u;

    float acc[4][4][4];
#pragma unroll
    for (int i = 0; i < 4; i++)
#pragma unroll
        for (int j = 0; j < 4; j++)
#pragma unroll
            for (int e = 0; e < 4; e++) acc[i][j][e] = 0.f;

    float4 pref[4];
    auto loadA = [&](int c) {
        int k0 = c * KC + ac * 16;
        int seg = k0 >> 8;
        int off = k0 & 255;
        const float4* zs = (const float4*)(g_z + (size_t)spi * Dd + off);
        const float4* zd = (const float4*)(g_z + (size_t)dpi * Dd + off);
#pragma unroll
        for (int j = 0; j < 4; j++) {
            if (!aok) { pref[j] = make_float4(0.f, 0.f, 0.f, 0.f); continue; }
            if (seg == 0) pref[j] = zs[j];
            else if (seg == 1) pref[j] = zd[j];
            else {
                float4 a = zs[j], b = zd[j];
                pref[j] = make_float4(a.x * b.x, a.y * b.y, a.z * b.z, a.w * b.w);
            }
        }
    };
    auto loadB = [&](int c, uint32_t stage) {
#pragma unroll
        for (int it = 0; it < 4; it++) {
            int idx = tid + it * 256;
            int half_ = idx >> 9;
            int r = idx & 511;
            int n = r >> 2, q = r & 3;
            const __half* srcb = half_ ? g_wtsl : g_wtsh;
            uint32_t dst = stage + (half_ ? B_LO : B_HI) + (uint32_t)n * 80u + (uint32_t)q * 16u;
            CP16(dst, srcb + (size_t)(n0 + n) * 768 + c * KC + q * 8);
        }
        CPCOMMIT();
    };

    loadA(0);
    loadB(0, sb);
#pragma unroll
    for (int j = 0; j < 4; j++) cvt_sts(sb + A_HI + asts + j * 8u, pref[j]);
    CPWAIT(0);
    __syncthreads();

    for (int c = 0; c < SCH; c++) {
        const int cn = c + 1;
        const uint32_t cur = sb + (uint32_t)(c & 1) * STAGE;
        const uint32_t nxt = sb + (uint32_t)(cn & 1) * STAGE;
        if (cn < SCH) { loadA(cn); loadB(cn, nxt); }
        mma_chunk32(cur, wm, wn, lane, acc);
        if (cn < SCH) {
#pragma unroll
            for (int j = 0; j < 4; j++)
                cvt_sts(nxt + A_HI + asts + j * 8u, pref[j]);
            CPWAIT(0);
        }
        __syncthreads();
    }

    // fused epilogue: h1 = BN(relu(acc + b1)); partial dot with w2; reduce; atomicAdd
    float part[4][2];
#pragma unroll
    for (int i = 0; i < 4; i++) { part[i][0] = 0.f; part[i][1] = 0.f; }

#pragma unroll
    for (int i = 0; i < 4; i++) {
        int mr = m0 + wm * 64 + i * 16 + (lane >> 2);
#pragma unroll
        for (int j = 0; j < 4; j++) {
            int col = n0 + wn * 32 + j * 8 + (lane & 3) * 2;
            float bia0 = b1[col], bia1 = b1[col + 1];
            float s0 = rsqrtf(bnv[col] + 1e-5f) * bng[col];
            float s1 = rsqrtf(bnv[col + 1] + 1e-5f) * bng[col + 1];
            float m0f = bnm[col], m1f = bnm[col + 1];
            float o0 = bnb[col], o1 = bnb[col + 1];
            float w0 = w2[col], w1 = w2[col + 1];
#pragma unroll
            for (int hh = 0; hh < 2; hh++) {
                int row = mr + hh * 8;
                if (row >= Pp) continue;
                float v0 = fmaxf(acc[i][j][hh * 2 + 0] + bia0, 0.f);
                float v1 = fmaxf(acc[i][j][hh * 2 + 1] + bia1, 0.f);
                v0 = (v0 - m0f) * s0 + o0;
                v1 = (v1 - m1f) * s1 + o1;
                part[i][hh] += v0 * w0 + v1 * w1;
            }
        }
    }
#pragma unroll
    for (int i = 0; i < 4; i++)
#pragma unroll
        for (int hh = 0; hh < 2; hh++) {
            float pv = part[i][hh];
            pv += __shfl_xor_sync(0xffffffffu, pv, 1);
            pv += __shfl_xor_sync(0xffffffffu, pv, 2);
            int row = m0 + wm * 64 + i * 16 + (lane >> 2) + hh * 8;
            if ((lane & 3) == 0 && row < Pp) atomicAdd(out + row, pv);
        }
}

// ---------------- final: bias + degree penalties (in-place on out) ----------------
__global__ void final2_k(const int* __restrict__ pairs,
                         const int* __restrict__ degrees,
                         const float* __restrict__ b2,
                         const float* __restrict__ alpha,
                         const float* __restrict__ beta,
                         float* __restrict__ out) {
    int p = blockIdx.x * blockDim.x + threadIdx.x;
    if (p >= Pp) return;
    float sc = out[p] + b2[0];
    int spi = pairs[p], dpi = pairs[Pp + p];
    float sd = fmaxf((float)degrees[spi], 1.f);
    float dd = fmaxf((float)degrees[dpi], 1.f);
    float ra = fmaxf(alpha[0], 0.f), rb = fmaxf(beta[0], 0.f);
    float base = sc - ra * logf(sd) - rb * logf(dd);
    out[p] = base / (sqrtf(sd) * sqrtf(dd) + 1e-8f);
}

// ---------------- fused LayerNorm + ReLU + residual -> xb0 fp16 ----------------
__global__ void ln_relu_add_k(const float* __restrict__ lng,
                              const float* __restrict__ lnb) {
    int n = blockIdx.x;
    int t = threadIdx.x;
    const float4 v = ((const float4*)(g_h + (size_t)n * Hh))[t];
    float s = v.x + v.y + v.z + v.w;
    float ss = v.x * v.x + v.y * v.y + v.z * v.z + v.w * v.w;
#pragma unroll
    for (int o = 16; o; o >>= 1) {
        s += __shfl_xor_sync(0xffffffff, s, o);
        ss += __shfl_xor_sync(0xffffffff, ss, o);
    }
    __shared__ float sm[4], sm2[4];
    if ((t & 31) == 0) { sm[t >> 5] = s; sm2[t >> 5] = ss; }
    __syncthreads();
    s = sm[0] + sm[1] + sm[2] + sm[3];
    ss = sm2[0] + sm2[1] + sm2[2] + sm2[3];
    float mu = s * (1.f / Hh);
    float var = ss * (1.f / Hh) - mu * mu;
    float rstd = rsqrtf(var + 1e-5f);
    float4 g = ((const float4*)lng)[t];
    float4 b = ((const float4*)lnb)[t];
    float4 xv = ((const float4*)(g_x2 + (size_t)n * Hh))[t];
    xv.x += fmaxf((v.x - mu) * rstd * g.x + b.x, 0.f);
    xv.y += fmaxf((v.y - mu) * rstd * g.y + b.y, 0.f);
    xv.z += fmaxf((v.z - mu) * rstd * g.z + b.z, 0.f);
    xv.w += fmaxf((v.w - mu) * rstd * g.w + b.w, 0.f);
    pack4_store(g_xb0 + (size_t)n * Hh + t * 4, xv);
}

// ---------------- side stream + events (created at static init) ----------------
namespace {
struct HxStreams {
    cudaStream_t s = nullptr;
    cudaEvent_t evRoot, evCSR, evW1, evW2, evW3, evWS;
    HxStreams() {
        cudaStreamCreateWithFlags(&s, cudaStreamNonBlocking);
        cudaEventCreateWithFlags(&evRoot, cudaEventDisableTiming);
        cudaEventCreateWithFlags(&evCSR, cudaEventDisableTiming);
        cudaEventCreateWithFlags(&evW1, cudaEventDisableTiming);
        cudaEventCreateWithFlags(&evW2, cudaEventDisableTiming);
        cudaEventCreateWithFlags(&evW3, cudaEventDisableTiming);
        cudaEventCreateWithFlags(&evWS, cudaEventDisableTiming);
    }
};
HxStreams g_hx;
}

// ---------------- launch ----------------
extern "C" void kernel_launch(void* const* d_in, const int* in_sizes, int n_in,
                              void* d_out, int out_size) {
    const int*   types     = (const int*)d_in[0];
    const int*   src0      = (const int*)d_in[1];
    const int*   dst0      = (const int*)d_in[2];
    const int*   src1      = (const int*)d_in[3];
    const int*   dst1      = (const int*)d_in[4];
    const int*   src2      = (const int*)d_in[5];
    const int*   dst2      = (const int*)d_in[6];
    const int*   pairs     = (const int*)d_in[7];
    const int*   degrees   = (const int*)d_in[8];
    const float* node_emb  = (const float*)d_in[9];
    const float* type_emb  = (const float*)d_in[10];
    const float* w_loop_in  = (const float*)d_in[11];
    const float* w_rel_in   = (const float*)d_in[12];
    const float* w_loop_res = (const float*)d_in[13];
    const float* w_rel_res  = (const float*)d_in[14];
    const float* ln_g       = (const float*)d_in[15];
    const float* ln_b       = (const float*)d_in[16];
    const float* w_loop_out = (const float*)d_in[17];
    const float* w_rel_out  = (const float*)d_in[18];
    const float* lp_w1      = (const float*)d_in[19];
    const float* lp_b1      = (const float*)d_in[20];
    const float* bn_g       = (const float*)d_in[21];
    const float* bn_b       = (const float*)d_in[22];
    const float* bn_mean    = (const float*)d_in[23];
    const float* bn_var     = (const float*)d_in[24];
    const float* lp_w2      = (const float*)d_in[25];
    const float* lp_b2      = (const float*)d_in[26];
    const float* alpha      = (const float*)d_in[27];
    const float* beta       = (const float*)d_in[28];
    float* out = (float*)d_out;

    float *px2, *ph, *pz;
    __half *pxb0, *pxb1;
    __half *pw1h, *pw1l, *pw2h, *pw2l, *pw3h, *pw3l;
    cudaGetSymbolAddress((void**)&px2,  g_x2);
    cudaGetSymbolAddress((void**)&ph,   g_h);
    cudaGetSymbolAddress((void**)&pz,   g_z);
    cudaGetSymbolAddress((void**)&pxb0, g_xb0);
    cudaGetSymbolAddress((void**)&pxb1, g_xb1);
    cudaGetSymbolAddress((void**)&pw1h, g_wt1h);
    cudaGetSymbolAddress((void**)&pw1l, g_wt1l);
    cudaGetSymbolAddress((void**)&pw2h, g_wt2h);
    cudaGetSymbolAddress((void**)&pw2l, g_wt2l);
    cudaGetSymbolAddress((void**)&pw3h, g_wt3h);
    cudaGetSymbolAddress((void**)&pw3l, g_wt3l);

    cudaFuncSetAttribute(rgcn_mma_k<512, 0>,
                         cudaFuncAttributeMaxDynamicSharedMemorySize, SMEM_TC);
    cudaFuncSetAttribute(rgcn_mma_k<512, 1>,
                         cudaFuncAttributeMaxDynamicSharedMemorySize, SMEM_TC);
    cudaFuncSetAttribute(rgcn_mma_k<256, 2>,
                         cudaFuncAttributeMaxDynamicSharedMemorySize, SMEM_TC);
    cudaFuncSetAttribute(score_mma_k,
                         cudaFuncAttributeMaxDynamicSharedMemorySize, SMEM_SC);

    const int ENC_BLKS = (Nn * (Hh / 4) + 255) / 256;
    const int E_BLKS   = (Ee + 255) / 256;
    const int Z_BLKS   = (3 * Nn + 255) / 256;
    const int P_BLKS   = (Pp + 255) / 256;
    const dim3 G1(512 / NTT, (Nn + MT - 1) / MT);
    const dim3 G3(256 / NTT, (Nn + MT - 1) / MT);
    const dim3 GSc(256 / NTT, (Pp + MT - 1) / MT);
    const dim3 GSCAN(SCNB, 3);
    const dim3 GWT512(KS / 32, 512 / 32);
    const dim3 GWT256(KS / 32, 256 / 32);
    const dim3 GWTS(768 / 32, 256 / 32);

    cudaStream_t sw = g_hx.s;

    cudaEventRecord(g_hx.evRoot, 0);
    cudaStreamWaitEvent(sw, g_hx.evRoot, 0);

    // ---- side stream: CSR build, weight splits, output zero ----
    csr_zero_k<<<Z_BLKS, 256, 0, sw>>>();
    csr_count_k<<<E_BLKS, 256, 0, sw>>>(dst0, dst1, dst2);
    csr_scan1_k<<<GSCAN, SCB, 0, sw>>>();
    csr_scan2_k<<<3, SCB, 0, sw>>>();
    csr_scan3_k<<<GSCAN, SCB, 0, sw>>>();
    csr_fill_k<<<E_BLKS, 256, 0, sw>>>(src0, dst0, src1, dst1, src2, dst2);
    cudaEventRecord(g_hx.evCSR, sw);
    wt_build_k<<<GWT512, 256, 0, sw>>>(w_loop_in, w_rel_in, 512, pw1h, pw1l);
    cudaEventRecord(g_hx.evW1, sw);
    wt_build_k<<<GWT512, 256, 0, sw>>>(w_loop_res, w_rel_res, 512, pw2h, pw2l);
    cudaEventRecord(g_hx.evW2, sw);
    wt_build_k<<<GWT256, 256, 0, sw>>>(w_loop_out, w_rel_out, 256, pw3h, pw3l);
    cudaEventRecord(g_hx.evW3, sw);
    wt_build_score_k<<<GWTS, 256, 0, sw>>>(lp_w1);
    zero_out_k<<<P_BLKS, 256, 0, sw>>>(out);
    cudaEventRecord(g_hx.evWS, sw);

    // ---- main stream: critical path ----
    encode_k<<<ENC_BLKS, 256>>>(types, node_emb, type_emb);

    cudaStreamWaitEvent(0, g_hx.evCSR, 0);
    agg_k<<<Nn, 128>>>(pxb0);
    cudaStreamWaitEvent(0, g_hx.evW1, 0);
    rgcn_mma_k<512, 0><<<G1, 256, SMEM_TC>>>(pxb0, pw1h, pw1l, px2, pxb1);

    agg_k<<<Nn, 128>>>(pxb1);
    cudaStreamWaitEvent(0, g_hx.evW2, 0);
    rgcn_mma_k<512, 1><<<G1, 256, SMEM_TC>>>(pxb1, pw2h, pw2l, ph, nullptr);
    ln_relu_add_k<<<Nn, 128>>>(ln_g, ln_b);

    agg_k<<<Nn, 128>>>(pxb0);
    cudaStreamWaitEvent(0, g_hx.evW3, 0);
    rgcn_mma_k<256, 2><<<G3, 256, SMEM_TC>>>(pxb0, pw3h, pw3l, pz, nullptr);

    // ---- scoring ----
    cudaStreamWaitEvent(0, g_hx.evWS, 0);
    score_mma_k<<<GSc, 256, SMEM_SC>>>(pairs, lp_b1, bn_g, bn_b, bn_mean, bn_var,
                                       lp_w2, out);
    final2_k<<<P_BLKS, 256>>>(pairs, degrees, lp_b2, alpha, beta, out);
}

// round 15
// speedup vs baseline: 1.0465x; 1.0465x over previous
#include <cuda_runtime.h>
#include <cuda_fp16.h>
#include <cstdint>

// Problem constants
#define Nn 50000
#define Hh 512
#define Dd 256
#define Ee 200000
#define Pp 100000
#define KS 2048   // 4*H stacked K dimension
#define AGGW 1536 // 3*H agg row width

// mma tile config
#define MT 128
#define NTT 128
#define KC 32
#define CHUNKS (KS / KC)    // 64
#define SCH (768 / KC)      // 24 (scoring K)

// smem stage layout (bytes): tiles stored [row][40 fp16] (80B pitch)
#define A_HI 0
#define B_HI 10240
#define B_LO 20480
#define STAGE 30720
#define SMEM_TC3 (3 * STAGE)   // 90KB -> 2 CTAs/SM
#define SMEM_SC  (2 * STAGE)

// CSR scan config
#define SCB 256
#define SCNB ((Nn + SCB - 1) / SCB)

// ---------------- scratch (device globals; no allocation) ----------------
__device__ float g_h [(size_t)Nn * Hh];
__device__ float g_z [(size_t)Nn * Dd];
__device__ __align__(16) __half g_xb0[(size_t)Nn * Hh];   // fp16 x (GEMM A + agg in)
__device__ __align__(16) __half g_xb1[(size_t)Nn * Hh];   // layer-1 out (also residual)
__device__ __align__(16) __half g_agg[(size_t)Nn * AGGW];
// per-layer weight buffers (hi/lo fp16, [HO][K])
__device__ __align__(16) __half g_wt1h[(size_t)512 * KS];
__device__ __align__(16) __half g_wt1l[(size_t)512 * KS];
__device__ __align__(16) __half g_wt2h[(size_t)512 * KS];
__device__ __align__(16) __half g_wt2l[(size_t)512 * KS];
__device__ __align__(16) __half g_wt3h[(size_t)256 * KS];
__device__ __align__(16) __half g_wt3l[(size_t)256 * KS];
__device__ __align__(16) __half g_wtsh[(size_t)256 * 768];
__device__ __align__(16) __half g_wtsl[(size_t)256 * 768];
// CSR
__device__ int g_deg  [3 * Nn];
__device__ int g_start[3 * Nn];
__device__ int g_cur  [3 * Nn];
__device__ int g_part [3 * SCNB];
__device__ int g_csr  [3 * (size_t)Ee];

// ======================= PTX helpers =======================
__device__ __forceinline__ uint32_t smem_u32(const void* p) {
    uint32_t a;
    asm("{ .reg .u64 t; cvta.to.shared.u64 t, %1; cvt.u32.u64 %0, t; }" : "=r"(a) : "l"(p));
    return a;
}
#define STS64(addr, val) \
    asm volatile("st.shared.b64 [%0], %1;" :: "r"(addr), "l"(val) : "memory")
#define CP16(dst, src) \
    asm volatile("cp.async.cg.shared.global [%0], [%1], 16;" :: "r"(dst), "l"(src) : "memory")
#define CPCOMMIT() asm volatile("cp.async.commit_group;" ::: "memory")
#define CPWAIT(n)  asm volatile("cp.async.wait_group %0;" :: "n"(n) : "memory")
#define LDSM_X4(r0, r1, r2, r3, addr) \
    asm volatile("ldmatrix.sync.aligned.m8n8.x4.shared.b16 {%0,%1,%2,%3},[%4];" \
                 : "=r"(r0), "=r"(r1), "=r"(r2), "=r"(r3) : "r"(addr))
#define MMA16816(d, a, b) \
    asm volatile("mma.sync.aligned.m16n8k16.row.col.f32.f16.f16.f32 " \
                 "{%0,%1,%2,%3},{%4,%5,%6,%7},{%8,%9},{%0,%1,%2,%3};" \
                 : "+f"((d)[0]), "+f"((d)[1]), "+f"((d)[2]), "+f"((d)[3]) \
                 : "r"((a)[0]), "r"((a)[1]), "r"((a)[2]), "r"((a)[3]), \
                   "r"((b)[0]), "r"((b)[1]))

// fp32 -> fp16 hi/lo split (weights)
__device__ __forceinline__ void split1h(float v, __half& h, __half& l) {
    h = __float2half(v);
    l = __float2half(v - __half2float(h));
}
__device__ __forceinline__ void pack4_store(__half* hp, float4 v) {
    __half2 h0 = __floats2half2_rn(v.x, v.y);
    __half2 h1 = __floats2half2_rn(v.z, v.w);
    uint2 u;
    u.x = *reinterpret_cast<uint32_t*>(&h0);
    u.y = *reinterpret_cast<uint32_t*>(&h1);
    *reinterpret_cast<uint2*>(hp) = u;
}
__device__ __forceinline__ void cvt_sts(uint32_t addr, float4 v) {
    __half2 h0 = __floats2half2_rn(v.x, v.y);
    __half2 h1 = __floats2half2_rn(v.z, v.w);
    uint32_t u0 = *reinterpret_cast<uint32_t*>(&h0);
    uint32_t u1 = *reinterpret_cast<uint32_t*>(&h1);
    STS64(addr, ((uint64_t)u1 << 32) | u0);
}
__device__ __forceinline__ void acc_h4(float4& acc, uint2 u) {
    __half2 a = *reinterpret_cast<__half2*>(&u.x);
    __half2 b = *reinterpret_cast<__half2*>(&u.y);
    float2 fa = __half22float2(a);
    float2 fb = __half22float2(b);
    acc.x += fa.x; acc.y += fa.y; acc.z += fb.x; acc.w += fb.y;
}

// one K-chunk (32) of fp16 2-pass mma for one warp
__device__ __forceinline__ void mma_chunk(uint32_t base, int wm, int wn, int lane,
                                          float acc[4][4][4]) {
#pragma unroll
    for (int ksf = 0; ksf < 2; ksf++) {
        uint32_t a_addr = base + A_HI +
                          (uint32_t)(wm * 64 + (lane & 15)) * 80u +
                          (uint32_t)(ksf * 16 + (lane >> 4) * 8) * 2u;
        uint32_t ah[4][4];
#pragma unroll
        for (int i = 0; i < 4; i++)
            LDSM_X4(ah[i][0], ah[i][1], ah[i][2], ah[i][3], a_addr + i * 16 * 80);
        int g = lane >> 3;
        uint32_t b_n = (uint32_t)(wn * 32 + ((g >> 1) << 3) + (lane & 7));
        uint32_t b_k = (uint32_t)(ksf * 16 + ((g & 1) << 3));
        uint32_t b_addr = base + B_HI + b_n * 80u + b_k * 2u;
        uint32_t bh[4][2], bl[4][2];
#pragma unroll
        for (int jp = 0; jp < 2; jp++) {
            LDSM_X4(bh[2 * jp][0], bh[2 * jp][1], bh[2 * jp + 1][0], bh[2 * jp + 1][1],
                    b_addr + jp * 16 * 80);
            LDSM_X4(bl[2 * jp][0], bl[2 * jp][1], bl[2 * jp + 1][0], bl[2 * jp + 1][1],
                    b_addr + 10240u + jp * 16 * 80);
        }
#pragma unroll
        for (int i = 0; i < 4; i++)
#pragma unroll
            for (int j = 0; j < 4; j++) {
                MMA16816(acc[i][j], ah[i], bh[j]);
                MMA16816(acc[i][j], ah[i], bl[j]);
            }
    }
}

// ---------------- encode: xb0 fp16 ----------------
__global__ void encode_k(const int* __restrict__ types,
                         const float* __restrict__ node_emb,
                         const float* __restrict__ type_emb) {
    int i = blockIdx.x * blockDim.x + threadIdx.x;
    if (i >= Nn * (Hh / 4)) return;
    int n = i >> 7;
    int q = i & 127;
    float4 a = ((const float4*)node_emb)[i];
    float4 b = ((const float4*)type_emb)[(size_t)types[n] * 128 + q];
    a.x += b.x; a.y += b.y; a.z += b.z; a.w += b.w;
    pack4_store(g_xb0 + (size_t)n * Hh + q * 4, a);
}

// ---------------- CSR build ----------------
__global__ void csr_zero_k() {
    int i = blockIdx.x * blockDim.x + threadIdx.x;
    if (i < 3 * Nn) { g_deg[i] = 0; g_cur[i] = 0; }
}
__global__ void csr_count_k(const int* __restrict__ d0, const int* __restrict__ d1,
                            const int* __restrict__ d2) {
    int e = blockIdx.x * blockDim.x + threadIdx.x;
    if (e >= Ee) return;
    atomicAdd(&g_deg[0 * Nn + d0[e]], 1);
    atomicAdd(&g_deg[1 * Nn + d1[e]], 1);
    atomicAdd(&g_deg[2 * Nn + d2[e]], 1);
}
__global__ void csr_scan1_k() {
    __shared__ int sm[SCB];
    int r = blockIdx.y;
    int i = blockIdx.x * SCB + threadIdx.x;
    sm[threadIdx.x] = (i < Nn) ? g_deg[r * Nn + i] : 0;
    __syncthreads();
    for (int o = SCB / 2; o; o >>= 1) {
        if (threadIdx.x < o) sm[threadIdx.x] += sm[threadIdx.x + o];
        __syncthreads();
    }
    if (threadIdx.x == 0) g_part[r * SCNB + blockIdx.x] = sm[0];
}
__global__ void csr_scan2_k() {
    __shared__ int sm[SCB];
    int r = blockIdx.x;
    int t = threadIdx.x;
    int v = (t < SCNB) ? g_part[r * SCNB + t] : 0;
    sm[t] = v;
    __syncthreads();
    for (int o = 1; o < SCB; o <<= 1) {
        int u = (t >= o) ? sm[t - o] : 0;
        __syncthreads();
        sm[t] += u;
        __syncthreads();
    }
    if (t < SCNB) g_part[r * SCNB + t] = sm[t] - v;
}
__global__ void csr_scan3_k() {
    __shared__ int sm[SCB];
    int r = blockIdx.y;
    int i = blockIdx.x * SCB + threadIdx.x;
    int v = (i < Nn) ? g_deg[r * Nn + i] : 0;
    sm[threadIdx.x] = v;
    __syncthreads();
    for (int o = 1; o < SCB; o <<= 1) {
        int t = (threadIdx.x >= o) ? sm[threadIdx.x - o] : 0;
        __syncthreads();
        sm[threadIdx.x] += t;
        __syncthreads();
    }
    if (i < Nn)
        g_start[r * Nn + i] = g_part[r * SCNB + blockIdx.x] + sm[threadIdx.x] - v;
}
__global__ void csr_fill_k(const int* __restrict__ s0, const int* __restrict__ d0,
                           const int* __restrict__ s1, const int* __restrict__ d1,
                           const int* __restrict__ s2, const int* __restrict__ d2) {
    int e = blockIdx.x * blockDim.x + threadIdx.x;
    if (e >= Ee) return;
    {
        int d = d0[e];
        int p = atomicAdd(&g_cur[0 * Nn + d], 1);
        g_csr[(size_t)0 * Ee + g_start[0 * Nn + d] + p] = s0[e];
    }
    {
        int d = d1[e];
        int p = atomicAdd(&g_cur[1 * Nn + d], 1);
        g_csr[(size_t)1 * Ee + g_start[1 * Nn + d] + p] = s1[e];
    }
    {
        int d = d2[e];
        int p = atomicAdd(&g_cur[2 * Nn + d], 1);
        g_csr[(size_t)2 * Ee + g_start[2 * Nn + d] + p] = s2[e];
    }
}

// ---------------- gather aggregation (fp16 in, fp16 out, MLP=4) ----------------
__global__ void agg_k(const __half* __restrict__ xin) {
    __shared__ int sl[128];
    const int n = blockIdx.x;
    const int r = blockIdx.y;
    const int t = threadIdx.x;   // 128; thread covers cols 4t..4t+3
    const int s = g_start[r * Nn + n];
    const int d = g_deg[r * Nn + n];
    const int* lst = g_csr + (size_t)r * Ee + s;
    float4 acc = make_float4(0.f, 0.f, 0.f, 0.f);
    for (int base = 0; base < d; base += 128) {
        int m = min(128, d - base);
        if (t < m) sl[t] = lst[base + t];
        __syncthreads();
        int i = 0;
        for (; i + 4 <= m; i += 4) {
            uint2 u0 = ((const uint2*)(xin + (size_t)sl[i + 0] * Hh))[t];
            uint2 u1 = ((const uint2*)(xin + (size_t)sl[i + 1] * Hh))[t];
            uint2 u2 = ((const uint2*)(xin + (size_t)sl[i + 2] * Hh))[t];
            uint2 u3 = ((const uint2*)(xin + (size_t)sl[i + 3] * Hh))[t];
            acc_h4(acc, u0); acc_h4(acc, u1); acc_h4(acc, u2); acc_h4(acc, u3);
        }
        for (; i < m; i++) {
            uint2 u = ((const uint2*)(xin + (size_t)sl[i] * Hh))[t];
            acc_h4(acc, u);
        }
        if (base + 128 < d) __syncthreads();
    }
    pack4_store(g_agg + (size_t)n * AGGW + r * Hh + t * 4, acc);
}

// ---------------- weight transpose + fp16 hi/lo split (tiled, coalesced) ----------------
__global__ void wt_build_k(const float* __restrict__ wl,
                           const float* __restrict__ wr, int HO,
                           __half* __restrict__ outh, __half* __restrict__ outl) {
    __shared__ float tile[32][33];
    int k0 = blockIdx.x * 32;
    int n0 = blockIdx.y * 32;
    int tx = threadIdx.x & 31, ty = threadIdx.x >> 5;
#pragma unroll
    for (int i = 0; i < 4; i++) {
        int k = k0 + ty + i * 8;
        int n = n0 + tx;
        float v = (k < Hh) ? wl[(size_t)k * HO + n] : wr[(size_t)(k - Hh) * HO + n];
        tile[ty + i * 8][tx] = v;
    }
    __syncthreads();
#pragma unroll
    for (int i = 0; i < 4; i++) {
        int n = n0 + ty + i * 8;
        int k = k0 + tx;
        float v = tile[tx][ty + i * 8];
        __half h, l;
        split1h(v, h, l);
        outh[(size_t)n * KS + k] = h;
        outl[(size_t)n * KS + k] = l;
    }
}
__global__ void wt_build_score_k(const float* __restrict__ w1) {
    __shared__ float tile[32][33];
    int k0 = blockIdx.x * 32;
    int n0 = blockIdx.y * 32;
    int tx = threadIdx.x & 31, ty = threadIdx.x >> 5;
#pragma unroll
    for (int i = 0; i < 4; i++) {
        int k = k0 + ty + i * 8;
        tile[ty + i * 8][tx] = w1[(size_t)k * 256 + n0 + tx];
    }
    __syncthreads();
#pragma unroll
    for (int i = 0; i < 4; i++) {
        int n = n0 + ty + i * 8;
        int k = k0 + tx;
        float v = tile[tx][ty + i * 8];
        __half h, l;
        split1h(v, h, l);
        g_wtsh[(size_t)n * 768 + k] = h;
        g_wtsl[(size_t)n * 768 + k] = l;
    }
}

// ---------------- RGCN GEMM (KC=32, 3-stage, 1 sync/chunk) ----------------
// MODE 0: relu, write fp16 oh only; MODE 1/2: write fp32 outf
template <int HO, int MODE>
__global__ void __launch_bounds__(256, 2) rgcn_mma_k(
    const __half* __restrict__ xh,
    const __half* __restrict__ wth, const __half* __restrict__ wtl,
    float* __restrict__ outf,
    __half* __restrict__ oh) {
    extern __shared__ char sm_[];
    const uint32_t sb = smem_u32(sm_);
    const int tid = threadIdx.x;
    const int wid = tid >> 5, lane = tid & 31;
    const int wm = wid & 1, wn = wid >> 1;
    const int m0 = blockIdx.y * MT;
    const int n0 = blockIdx.x * NTT;

    auto load_stage = [&](int c) {
        uint32_t stage = sb + (uint32_t)(c % 3) * STAGE;
        int colA = c * KC;
#pragma unroll
        for (int u = 0; u < 2; u++) {
            int idx = tid * 2 + u;
            int row = idx >> 2, q = idx & 3;
            uint32_t d = stage + (uint32_t)row * 80u + (uint32_t)q * 16u;
            int gr = m0 + row;
            if (gr >= Nn) gr = Nn - 1;
            const __half* ah;
            if (colA < Hh) {
                ah = xh + (size_t)gr * Hh + colA + q * 8;
            } else {
                ah = g_agg + (size_t)gr * AGGW + (colA - Hh) + q * 8;
            }
            CP16(d + A_HI, ah);
            size_t ob = (size_t)(n0 + row) * KS + colA + q * 8;
            CP16(d + B_HI, wth + ob);
            CP16(d + B_LO, wtl + ob);
        }
        CPCOMMIT();
    };

    float acc[4][4][4];
#pragma unroll
    for (int i = 0; i < 4; i++)
#pragma unroll
        for (int j = 0; j < 4; j++)
#pragma unroll
            for (int e = 0; e < 4; e++) acc[i][j][e] = 0.f;

    load_stage(0);
    load_stage(1);

    for (int c = 0; c < CHUNKS; c++) {
        if (c + 1 < CHUNKS) { CPWAIT(1); } else { CPWAIT(0); }
        __syncthreads();
        if (c + 2 < CHUNKS) load_stage(c + 2);
        mma_chunk(sb + (uint32_t)(c % 3) * STAGE, wm, wn, lane, acc);
    }

#pragma unroll
    for (int i = 0; i < 4; i++) {
        int mr = m0 + wm * 64 + i * 16 + (lane >> 2);
#pragma unroll
        for (int j = 0; j < 4; j++) {
            int col = n0 + wn * 32 + j * 8 + (lane & 3) * 2;
#pragma unroll
            for (int hh = 0; hh < 2; hh++) {
                int row = mr + hh * 8;
                if (row >= Nn) continue;
                float v0 = acc[i][j][hh * 2 + 0];
                float v1 = acc[i][j][hh * 2 + 1];
                if (MODE == 0) {
                    v0 = fmaxf(v0, 0.f);
                    v1 = fmaxf(v1, 0.f);
                    __half2 hp = __floats2half2_rn(v0, v1);
                    *(uint32_t*)(oh + (size_t)row * Hh + col) =
                        *reinterpret_cast<uint32_t*>(&hp);
                } else {
                    *(float2*)(outf + (size_t)row * HO + col) = make_float2(v0, v1);
                }
            }
        }
    }
}

// ---------------- zero output ----------------
__global__ void zero_out_k(float* __restrict__ out) {
    int p = blockIdx.x * blockDim.x + threadIdx.x;
    if (p < Pp) out[p] = 0.f;
}

// ---------------- scoring GEMM (gathered A, cvt in-kernel, 2-stage, fused dot) ----------------
__global__ void __launch_bounds__(256, 2) score_mma_k(const int* __restrict__ pairs,
                                                      const float* __restrict__ b1,
                                                      const float* __restrict__ bng,
                                                      const float* __restrict__ bnb,
                                                      const float* __restrict__ bnm,
                                                      const float* __restrict__ bnv,
                                                      const float* __restrict__ w2,
                                                      float* __restrict__ out) {
    extern __shared__ char sm_[];
    const uint32_t sb = smem_u32(sm_);
    const int tid = threadIdx.x;
    const int wid = tid >> 5, lane = tid & 31;
    const int wm = wid & 1, wn = wid >> 1;
    const int m0 = blockIdx.y * MT;
    const int n0 = blockIdx.x * NTT;

    const int ar = tid >> 1;
    const int ac = tid & 1;
    const int p = m0 + ar;
    const bool aok = p < Pp;
    const int spi = aok ? pairs[p] : 0;
    const int dpi = aok ? pairs[Pp + p] : 0;
    const uint32_t asts = (uint32_t)ar * 80u + (uint32_t)ac * 32u;

    float acc[4][4][4];
#pragma unroll
    for (int i = 0; i < 4; i++)
#pragma unroll
        for (int j = 0; j < 4; j++)
#pragma unroll
            for (int e = 0; e < 4; e++) acc[i][j][e] = 0.f;

    float4 pref[4];
    auto loadA = [&](int c) {
        int k0 = c * KC + ac * 16;
        int seg = k0 >> 8;
        int off = k0 & 255;
        const float4* zs = (const float4*)(g_z + (size_t)spi * Dd + off);
        const float4* zd = (const float4*)(g_z + (size_t)dpi * Dd + off);
#pragma unroll
        for (int j = 0; j < 4; j++) {
            if (!aok) { pref[j] = make_float4(0.f, 0.f, 0.f, 0.f); continue; }
            if (seg == 0) pref[j] = zs[j];
            else if (seg == 1) pref[j] = zd[j];
            else {
                float4 a = zs[j], b = zd[j];
                pref[j] = make_float4(a.x * b.x, a.y * b.y, a.z * b.z, a.w * b.w);
            }
        }
    };
    auto loadB = [&](int c, uint32_t stage) {
#pragma unroll
        for (int it = 0; it < 4; it++) {
            int idx = tid + it * 256;
            int half_ = idx >> 9;
            int r = idx & 511;
            int n = r >> 2, q = r & 3;
            const __half* srcb = half_ ? g_wtsl : g_wtsh;
            uint32_t dst = stage + (half_ ? B_LO : B_HI) + (uint32_t)n * 80u + (uint32_t)q * 16u;
            CP16(dst, srcb + (size_t)(n0 + n) * 768 + c * KC + q * 8);
        }
        CPCOMMIT();
    };

    loadA(0);
    loadB(0, sb);
#pragma unroll
    for (int j = 0; j < 4; j++) cvt_sts(sb + A_HI + asts + j * 8u, pref[j]);
    CPWAIT(0);
    __syncthreads();

    for (int c = 0; c < SCH; c++) {
        const int cn = c + 1;
        const uint32_t cur = sb + (uint32_t)(c & 1) * STAGE;
        const uint32_t nxt = sb + (uint32_t)(cn & 1) * STAGE;
        if (cn < SCH) { loadA(cn); loadB(cn, nxt); }
        mma_chunk(cur, wm, wn, lane, acc);
        if (cn < SCH) {
#pragma unroll
            for (int j = 0; j < 4; j++)
                cvt_sts(nxt + A_HI + asts + j * 8u, pref[j]);
            CPWAIT(0);
        }
        __syncthreads();
    }

    // fused epilogue: h1 = BN(relu(acc + b1)); partial dot with w2; reduce; atomicAdd
    float part[4][2];
#pragma unroll
    for (int i = 0; i < 4; i++) { part[i][0] = 0.f; part[i][1] = 0.f; }

#pragma unroll
    for (int i = 0; i < 4; i++) {
        int mr = m0 + wm * 64 + i * 16 + (lane >> 2);
#pragma unroll
        for (int j = 0; j < 4; j++) {
            int col = n0 + wn * 32 + j * 8 + (lane & 3) * 2;
            float bia0 = b1[col], bia1 = b1[col + 1];
            float s0 = rsqrtf(bnv[col] + 1e-5f) * bng[col];
            float s1 = rsqrtf(bnv[col + 1] + 1e-5f) * bng[col + 1];
            float m0f = bnm[col], m1f = bnm[col + 1];
            float o0 = bnb[col], o1 = bnb[col + 1];
            float w0 = w2[col], w1 = w2[col + 1];
#pragma unroll
            for (int hh = 0; hh < 2; hh++) {
                int row = mr + hh * 8;
                if (row >= Pp) continue;
                float v0 = fmaxf(acc[i][j][hh * 2 + 0] + bia0, 0.f);
                float v1 = fmaxf(acc[i][j][hh * 2 + 1] + bia1, 0.f);
                v0 = (v0 - m0f) * s0 + o0;
                v1 = (v1 - m1f) * s1 + o1;
                part[i][hh] += v0 * w0 + v1 * w1;
            }
        }
    }
#pragma unroll
    for (int i = 0; i < 4; i++)
#pragma unroll
        for (int hh = 0; hh < 2; hh++) {
            float pv = part[i][hh];
            pv += __shfl_xor_sync(0xffffffffu, pv, 1);
            pv += __shfl_xor_sync(0xffffffffu, pv, 2);
            int row = m0 + wm * 64 + i * 16 + (lane >> 2) + hh * 8;
            if ((lane & 3) == 0 && row < Pp) atomicAdd(out + row, pv);
        }
}

// ---------------- final: bias + degree penalties (in-place on out) ----------------
__global__ void final2_k(const int* __restrict__ pairs,
                         const int* __restrict__ degrees,
                         const float* __restrict__ b2,
                         const float* __restrict__ alpha,
                         const float* __restrict__ beta,
                         float* __restrict__ out) {
    int p = blockIdx.x * blockDim.x + threadIdx.x;
    if (p >= Pp) return;
    float sc = out[p] + b2[0];
    int spi = pairs[p], dpi = pairs[Pp + p];
    float sd = fmaxf((float)degrees[spi], 1.f);
    float dd = fmaxf((float)degrees[dpi], 1.f);
    float ra = fmaxf(alpha[0], 0.f), rb = fmaxf(beta[0], 0.f);
    float base = sc - ra * logf(sd) - rb * logf(dd);
    out[p] = base / (sqrtf(sd) * sqrtf(dd) + 1e-8f);
}

// ---------------- fused LayerNorm + ReLU + residual(xb1 fp16) -> xb0 fp16 ----------------
__global__ void ln_relu_add_k(const float* __restrict__ lng,
                              const float* __restrict__ lnb) {
    int n = blockIdx.x;
    int t = threadIdx.x;
    const float4 v = ((const float4*)(g_h + (size_t)n * Hh))[t];
    float s = v.x + v.y + v.z + v.w;
    float ss = v.x * v.x + v.y * v.y + v.z * v.z + v.w * v.w;
#pragma unroll
    for (int o = 16; o; o >>= 1) {
        s += __shfl_xor_sync(0xffffffff, s, o);
        ss += __shfl_xor_sync(0xffffffff, ss, o);
    }
    __shared__ float sm[4], sm2[4];
    if ((t & 31) == 0) { sm[t >> 5] = s; sm2[t >> 5] = ss; }
    __syncthreads();
    s = sm[0] + sm[1] + sm[2] + sm[3];
    ss = sm2[0] + sm2[1] + sm2[2] + sm2[3];
    float mu = s * (1.f / Hh);
    float var = ss * (1.f / Hh) - mu * mu;
    float rstd = rsqrtf(var + 1e-5f);
    float4 g = ((const float4*)lng)[t];
    float4 b = ((const float4*)lnb)[t];
    // residual from fp16 xb1
    uint2 ru = ((const uint2*)(g_xb1 + (size_t)n * Hh))[t];
    __half2 r0 = *reinterpret_cast<__half2*>(&ru.x);
    __half2 r1 = *reinterpret_cast<__half2*>(&ru.y);
    float2 f0 = __half22float2(r0);
    float2 f1 = __half22float2(r1);
    float4 xv = make_float4(f0.x, f0.y, f1.x, f1.y);
    xv.x += fmaxf((v.x - mu) * rstd * g.x + b.x, 0.f);
    xv.y += fmaxf((v.y - mu) * rstd * g.y + b.y, 0.f);
    xv.z += fmaxf((v.z - mu) * rstd * g.z + b.z, 0.f);
    xv.w += fmaxf((v.w - mu) * rstd * g.w + b.w, 0.f);
    pack4_store(g_xb0 + (size_t)n * Hh + t * 4, xv);
}

// ---------------- side stream + events (created at static init) ----------------
namespace {
struct HxStreams {
    cudaStream_t s = nullptr;
    cudaEvent_t evRoot, evCSR, evW1, evW2, evW3, evWS;
    HxStreams() {
        cudaStreamCreateWithFlags(&s, cudaStreamNonBlocking);
        cudaEventCreateWithFlags(&evRoot, cudaEventDisableTiming);
        cudaEventCreateWithFlags(&evCSR, cudaEventDisableTiming);
        cudaEventCreateWithFlags(&evW1, cudaEventDisableTiming);
        cudaEventCreateWithFlags(&evW2, cudaEventDisableTiming);
        cudaEventCreateWithFlags(&evW3, cudaEventDisableTiming);
        cudaEventCreateWithFlags(&evWS, cudaEventDisableTiming);
    }
};
HxStreams g_hx;
}

// ---------------- launch ----------------
extern "C" void kernel_launch(void* const* d_in, const int* in_sizes, int n_in,
                              void* d_out, int out_size) {
    const int*   types     = (const int*)d_in[0];
    const int*   src0      = (const int*)d_in[1];
    const int*   dst0      = (const int*)d_in[2];
    const int*   src1      = (const int*)d_in[3];
    const int*   dst1      = (const int*)d_in[4];
    const int*   src2      = (const int*)d_in[5];
    const int*   dst2      = (const int*)d_in[6];
    const int*   pairs     = (const int*)d_in[7];
    const int*   degrees   = (const int*)d_in[8];
    const float* node_emb  = (const float*)d_in[9];
    const float* type_emb  = (const float*)d_in[10];
    const float* w_loop_in  = (const float*)d_in[11];
    const float* w_rel_in   = (const float*)d_in[12];
    const float* w_loop_res = (const float*)d_in[13];
    const float* w_rel_res  = (const float*)d_in[14];
    const float* ln_g       = (const float*)d_in[15];
    const float* ln_b       = (const float*)d_in[16];
    const float* w_loop_out = (const float*)d_in[17];
    const float* w_rel_out  = (const float*)d_in[18];
    const float* lp_w1      = (const float*)d_in[19];
    const float* lp_b1      = (const float*)d_in[20];
    const float* bn_g       = (const float*)d_in[21];
    const float* bn_b       = (const float*)d_in[22];
    const float* bn_mean    = (const float*)d_in[23];
    const float* bn_var     = (const float*)d_in[24];
    const float* lp_w2      = (const float*)d_in[25];
    const float* lp_b2      = (const float*)d_in[26];
    const float* alpha      = (const float*)d_in[27];
    const float* beta       = (const float*)d_in[28];
    float* out = (float*)d_out;

    float *ph, *pz;
    __half *pxb0, *pxb1;
    __half *pw1h, *pw1l, *pw2h, *pw2l, *pw3h, *pw3l;
    cudaGetSymbolAddress((void**)&ph,   g_h);
    cudaGetSymbolAddress((void**)&pz,   g_z);
    cudaGetSymbolAddress((void**)&pxb0, g_xb0);
    cudaGetSymbolAddress((void**)&pxb1, g_xb1);
    cudaGetSymbolAddress((void**)&pw1h, g_wt1h);
    cudaGetSymbolAddress((void**)&pw1l, g_wt1l);
    cudaGetSymbolAddress((void**)&pw2h, g_wt2h);
    cudaGetSymbolAddress((void**)&pw2l, g_wt2l);
    cudaGetSymbolAddress((void**)&pw3h, g_wt3h);
    cudaGetSymbolAddress((void**)&pw3l, g_wt3l);

    cudaFuncSetAttribute(rgcn_mma_k<512, 0>,
                         cudaFuncAttributeMaxDynamicSharedMemorySize, SMEM_TC3);
    cudaFuncSetAttribute(rgcn_mma_k<512, 1>,
                         cudaFuncAttributeMaxDynamicSharedMemorySize, SMEM_TC3);
    cudaFuncSetAttribute(rgcn_mma_k<256, 2>,
                         cudaFuncAttributeMaxDynamicSharedMemorySize, SMEM_TC3);
    cudaFuncSetAttribute(score_mma_k,
                         cudaFuncAttributeMaxDynamicSharedMemorySize, SMEM_SC);

    const int ENC_BLKS = (Nn * (Hh / 4) + 255) / 256;
    const int E_BLKS   = (Ee + 255) / 256;
    const int Z_BLKS   = (3 * Nn + 255) / 256;
    const int P_BLKS   = (Pp + 255) / 256;
    const dim3 G1(512 / NTT, (Nn + MT - 1) / MT);
    const dim3 G3(256 / NTT, (Nn + MT - 1) / MT);
    const dim3 GSc(256 / NTT, (Pp + MT - 1) / MT);
    const dim3 GAGG(Nn, 3);
    const dim3 GSCAN(SCNB, 3);
    const dim3 GWT512(KS / 32, 512 / 32);
    const dim3 GWT256(KS / 32, 256 / 32);
    const dim3 GWTS(768 / 32, 256 / 32);

    cudaStream_t sw = g_hx.s;

    cudaEventRecord(g_hx.evRoot, 0);
    cudaStreamWaitEvent(sw, g_hx.evRoot, 0);

    // ---- side stream: CSR build, weight splits, output zero ----
    csr_zero_k<<<Z_BLKS, 256, 0, sw>>>();
    csr_count_k<<<E_BLKS, 256, 0, sw>>>(dst0, dst1, dst2);
    csr_scan1_k<<<GSCAN, SCB, 0, sw>>>();
    csr_scan2_k<<<3, SCB, 0, sw>>>();
    csr_scan3_k<<<GSCAN, SCB, 0, sw>>>();
    csr_fill_k<<<E_BLKS, 256, 0, sw>>>(src0, dst0, src1, dst1, src2, dst2);
    cudaEventRecord(g_hx.evCSR, sw);
    wt_build_k<<<GWT512, 256, 0, sw>>>(w_loop_in, w_rel_in, 512, pw1h, pw1l);
    cudaEventRecord(g_hx.evW1, sw);
    wt_build_k<<<GWT512, 256, 0, sw>>>(w_loop_res, w_rel_res, 512, pw2h, pw2l);
    cudaEventRecord(g_hx.evW2, sw);
    wt_build_k<<<GWT256, 256, 0, sw>>>(w_loop_out, w_rel_out, 256, pw3h, pw3l);
    cudaEventRecord(g_hx.evW3, sw);
    wt_build_score_k<<<GWTS, 256, 0, sw>>>(lp_w1);
    zero_out_k<<<P_BLKS, 256, 0, sw>>>(out);
    cudaEventRecord(g_hx.evWS, sw);

    // ---- main stream: critical path ----
    encode_k<<<ENC_BLKS, 256>>>(types, node_emb, type_emb);

    cudaStreamWaitEvent(0, g_hx.evCSR, 0);
    agg_k<<<GAGG, 128>>>(pxb0);
    cudaStreamWaitEvent(0, g_hx.evW1, 0);
    rgcn_mma_k<512, 0><<<G1, 256, SMEM_TC3>>>(pxb0, pw1h, pw1l, nullptr, pxb1);

    agg_k<<<GAGG, 128>>>(pxb1);
    cudaStreamWaitEvent(0, g_hx.evW2, 0);
    rgcn_mma_k<512, 1><<<G1, 256, SMEM_TC3>>>(pxb1, pw2h, pw2l, ph, nullptr);
    ln_relu_add_k<<<Nn, 128>>>(ln_g, ln_b);

    agg_k<<<GAGG, 128>>>(pxb0);
    cudaStreamWaitEvent(0, g_hx.evW3, 0);
    rgcn_mma_k<256, 2><<<G3, 256, SMEM_TC3>>>(pxb0, pw3h, pw3l, pz, nullptr);

    // ---- scoring ----
    cudaStreamWaitEvent(0, g_hx.evWS, 0);
    score_mma_k<<<GSc, 256, SMEM_SC>>>(pairs, lp_b1, bn_g, bn_b, bn_mean, bn_var,
                                       lp_w2, out);
    final2_k<<<P_BLKS, 256>>>(pairs, degrees, lp_b2, alpha, beta, out);
}

// round 16
// speedup vs baseline: 1.0492x; 1.0025x over previous
#include <cuda_runtime.h>
#include <cuda_fp16.h>
#include <cstdint>

// Problem constants
#define Nn 50000
#define Hh 512
#define Dd 256
#define Ee 200000
#define Pp 100000
#define KS 2048   // 4*H stacked K dimension
#define AGGW 1536 // 3*H agg row width

// mma tile config
#define MT 128
#define NTT 128
#define KC 32
#define CHUNKS (KS / KC)    // 64
#define SCH (768 / KC)      // 24 (scoring K)

// smem stage layout (bytes): tiles stored [row][40 fp16] (80B pitch)
#define A_HI 0
#define B_HI 10240
#define B_LO 20480
#define STAGE 30720
#define SMEM_TC3 (3 * STAGE)   // 90KB -> 2 CTAs/SM
#define SMEM_SC  (2 * STAGE)

// CSR scan config
#define SCB 256
#define SCNB ((Nn + SCB - 1) / SCB)

// ---------------- scratch (device globals; no allocation) ----------------
__device__ float g_z [(size_t)Nn * Dd];
__device__ __align__(16) __half g_hb [(size_t)Nn * Hh];   // fp16 layer-2 pre-LN
__device__ __align__(16) __half g_xb0[(size_t)Nn * Hh];   // fp16 x (GEMM A + agg in)
__device__ __align__(16) __half g_xb1[(size_t)Nn * Hh];   // layer-1 out (also residual)
__device__ __align__(16) __half g_agg[(size_t)Nn * AGGW];
// per-layer weight buffers (hi/lo fp16, [HO][K])
__device__ __align__(16) __half g_wt1h[(size_t)512 * KS];
__device__ __align__(16) __half g_wt1l[(size_t)512 * KS];
__device__ __align__(16) __half g_wt2h[(size_t)512 * KS];
__device__ __align__(16) __half g_wt2l[(size_t)512 * KS];
__device__ __align__(16) __half g_wt3h[(size_t)256 * KS];
__device__ __align__(16) __half g_wt3l[(size_t)256 * KS];
__device__ __align__(16) __half g_wtsh[(size_t)256 * 768];
__device__ __align__(16) __half g_wtsl[(size_t)256 * 768];
// CSR
__device__ int g_deg  [3 * Nn];
__device__ int g_start[3 * Nn];
__device__ int g_cur  [3 * Nn];
__device__ int g_part [3 * SCNB];
__device__ int g_csr  [3 * (size_t)Ee];

// ======================= PTX helpers =======================
__device__ __forceinline__ uint32_t smem_u32(const void* p) {
    uint32_t a;
    asm("{ .reg .u64 t; cvta.to.shared.u64 t, %1; cvt.u32.u64 %0, t; }" : "=r"(a) : "l"(p));
    return a;
}
#define STS64(addr, val) \
    asm volatile("st.shared.b64 [%0], %1;" :: "r"(addr), "l"(val) : "memory")
#define CP16(dst, src) \
    asm volatile("cp.async.cg.shared.global [%0], [%1], 16;" :: "r"(dst), "l"(src) : "memory")
#define CPCOMMIT() asm volatile("cp.async.commit_group;" ::: "memory")
#define CPWAIT(n)  asm volatile("cp.async.wait_group %0;" :: "n"(n) : "memory")
#define LDSM_X4(r0, r1, r2, r3, addr) \
    asm volatile("ldmatrix.sync.aligned.m8n8.x4.shared.b16 {%0,%1,%2,%3},[%4];" \
                 : "=r"(r0), "=r"(r1), "=r"(r2), "=r"(r3) : "r"(addr))
#define MMA16816(d, a, b) \
    asm volatile("mma.sync.aligned.m16n8k16.row.col.f32.f16.f16.f32 " \
                 "{%0,%1,%2,%3},{%4,%5,%6,%7},{%8,%9},{%0,%1,%2,%3};" \
                 : "+f"((d)[0]), "+f"((d)[1]), "+f"((d)[2]), "+f"((d)[3]) \
                 : "r"((a)[0]), "r"((a)[1]), "r"((a)[2]), "r"((a)[3]), \
                   "r"((b)[0]), "r"((b)[1]))

// fp32 -> fp16 hi/lo split (weights)
__device__ __forceinline__ void split1h(float v, __half& h, __half& l) {
    h = __float2half(v);
    l = __float2half(v - __half2float(h));
}
__device__ __forceinline__ void pack4_store(__half* hp, float4 v) {
    __half2 h0 = __floats2half2_rn(v.x, v.y);
    __half2 h1 = __floats2half2_rn(v.z, v.w);
    uint2 u;
    u.x = *reinterpret_cast<uint32_t*>(&h0);
    u.y = *reinterpret_cast<uint32_t*>(&h1);
    *reinterpret_cast<uint2*>(hp) = u;
}
__device__ __forceinline__ void cvt_sts(uint32_t addr, float4 v) {
    __half2 h0 = __floats2half2_rn(v.x, v.y);
    __half2 h1 = __floats2half2_rn(v.z, v.w);
    uint32_t u0 = *reinterpret_cast<uint32_t*>(&h0);
    uint32_t u1 = *reinterpret_cast<uint32_t*>(&h1);
    STS64(addr, ((uint64_t)u1 << 32) | u0);
}
__device__ __forceinline__ void acc_h4(float4& acc, uint2 u) {
    __half2 a = *reinterpret_cast<__half2*>(&u.x);
    __half2 b = *reinterpret_cast<__half2*>(&u.y);
    float2 fa = __half22float2(a);
    float2 fb = __half22float2(b);
    acc.x += fa.x; acc.y += fa.y; acc.z += fb.x; acc.w += fb.y;
}
__device__ __forceinline__ float4 h4_to_f4(uint2 u) {
    __half2 a = *reinterpret_cast<__half2*>(&u.x);
    __half2 b = *reinterpret_cast<__half2*>(&u.y);
    float2 fa = __half22float2(a);
    float2 fb = __half22float2(b);
    return make_float4(fa.x, fa.y, fb.x, fb.y);
}

// one K-chunk (32) of fp16 2-pass mma for one warp
__device__ __forceinline__ void mma_chunk(uint32_t base, int wm, int wn, int lane,
                                          float acc[4][4][4]) {
#pragma unroll
    for (int ksf = 0; ksf < 2; ksf++) {
        uint32_t a_addr = base + A_HI +
                          (uint32_t)(wm * 64 + (lane & 15)) * 80u +
                          (uint32_t)(ksf * 16 + (lane >> 4) * 8) * 2u;
        uint32_t ah[4][4];
#pragma unroll
        for (int i = 0; i < 4; i++)
            LDSM_X4(ah[i][0], ah[i][1], ah[i][2], ah[i][3], a_addr + i * 16 * 80);
        int g = lane >> 3;
        uint32_t b_n = (uint32_t)(wn * 32 + ((g >> 1) << 3) + (lane & 7));
        uint32_t b_k = (uint32_t)(ksf * 16 + ((g & 1) << 3));
        uint32_t b_addr = base + B_HI + b_n * 80u + b_k * 2u;
        uint32_t bh[4][2], bl[4][2];
#pragma unroll
        for (int jp = 0; jp < 2; jp++) {
            LDSM_X4(bh[2 * jp][0], bh[2 * jp][1], bh[2 * jp + 1][0], bh[2 * jp + 1][1],
                    b_addr + jp * 16 * 80);
            LDSM_X4(bl[2 * jp][0], bl[2 * jp][1], bl[2 * jp + 1][0], bl[2 * jp + 1][1],
                    b_addr + 10240u + jp * 16 * 80);
        }
#pragma unroll
        for (int i = 0; i < 4; i++)
#pragma unroll
            for (int j = 0; j < 4; j++) {
                MMA16816(acc[i][j], ah[i], bh[j]);
                MMA16816(acc[i][j], ah[i], bl[j]);
            }
    }
}

// ---------------- encode: xb0 fp16 ----------------
__global__ void encode_k(const int* __restrict__ types,
                         const float* __restrict__ node_emb,
                         const float* __restrict__ type_emb) {
    int i = blockIdx.x * blockDim.x + threadIdx.x;
    if (i >= Nn * (Hh / 4)) return;
    int n = i >> 7;
    int q = i & 127;
    float4 a = ((const float4*)node_emb)[i];
    float4 b = ((const float4*)type_emb)[(size_t)types[n] * 128 + q];
    a.x += b.x; a.y += b.y; a.z += b.z; a.w += b.w;
    pack4_store(g_xb0 + (size_t)n * Hh + q * 4, a);
}

// ---------------- CSR build ----------------
__global__ void csr_zero_k() {
    int i = blockIdx.x * blockDim.x + threadIdx.x;
    if (i < 3 * Nn) { g_deg[i] = 0; g_cur[i] = 0; }
}
__global__ void csr_count_k(const int* __restrict__ d0, const int* __restrict__ d1,
                            const int* __restrict__ d2) {
    int e = blockIdx.x * blockDim.x + threadIdx.x;
    if (e >= Ee) return;
    atomicAdd(&g_deg[0 * Nn + d0[e]], 1);
    atomicAdd(&g_deg[1 * Nn + d1[e]], 1);
    atomicAdd(&g_deg[2 * Nn + d2[e]], 1);
}
__global__ void csr_scan1_k() {
    __shared__ int sm[SCB];
    int r = blockIdx.y;
    int i = blockIdx.x * SCB + threadIdx.x;
    sm[threadIdx.x] = (i < Nn) ? g_deg[r * Nn + i] : 0;
    __syncthreads();
    for (int o = SCB / 2; o; o >>= 1) {
        if (threadIdx.x < o) sm[threadIdx.x] += sm[threadIdx.x + o];
        __syncthreads();
    }
    if (threadIdx.x == 0) g_part[r * SCNB + blockIdx.x] = sm[0];
}
__global__ void csr_scan2_k() {
    __shared__ int sm[SCB];
    int r = blockIdx.x;
    int t = threadIdx.x;
    int v = (t < SCNB) ? g_part[r * SCNB + t] : 0;
    sm[t] = v;
    __syncthreads();
    for (int o = 1; o < SCB; o <<= 1) {
        int u = (t >= o) ? sm[t - o] : 0;
        __syncthreads();
        sm[t] += u;
        __syncthreads();
    }
    if (t < SCNB) g_part[r * SCNB + t] = sm[t] - v;
}
__global__ void csr_scan3_k() {
    __shared__ int sm[SCB];
    int r = blockIdx.y;
    int i = blockIdx.x * SCB + threadIdx.x;
    int v = (i < Nn) ? g_deg[r * Nn + i] : 0;
    sm[threadIdx.x] = v;
    __syncthreads();
    for (int o = 1; o < SCB; o <<= 1) {
        int t = (threadIdx.x >= o) ? sm[threadIdx.x - o] : 0;
        __syncthreads();
        sm[threadIdx.x] += t;
        __syncthreads();
    }
    if (i < Nn)
        g_start[r * Nn + i] = g_part[r * SCNB + blockIdx.x] + sm[threadIdx.x] - v;
}
__global__ void csr_fill_k(const int* __restrict__ s0, const int* __restrict__ d0,
                           const int* __restrict__ s1, const int* __restrict__ d1,
                           const int* __restrict__ s2, const int* __restrict__ d2) {
    int e = blockIdx.x * blockDim.x + threadIdx.x;
    if (e >= Ee) return;
    {
        int d = d0[e];
        int p = atomicAdd(&g_cur[0 * Nn + d], 1);
        g_csr[(size_t)0 * Ee + g_start[0 * Nn + d] + p] = s0[e];
    }
    {
        int d = d1[e];
        int p = atomicAdd(&g_cur[1 * Nn + d], 1);
        g_csr[(size_t)1 * Ee + g_start[1 * Nn + d] + p] = s1[e];
    }
    {
        int d = d2[e];
        int p = atomicAdd(&g_cur[2 * Nn + d], 1);
        g_csr[(size_t)2 * Ee + g_start[2 * Nn + d] + p] = s2[e];
    }
}

// ---------------- gather aggregation (fp16 in, fp16 out, MLP=4) ----------------
__global__ void agg_k(const __half* __restrict__ xin) {
    __shared__ int sl[128];
    const int n = blockIdx.x;
    const int r = blockIdx.y;
    const int t = threadIdx.x;   // 128; thread covers cols 4t..4t+3
    const int s = g_start[r * Nn + n];
    const int d = g_deg[r * Nn + n];
    const int* lst = g_csr + (size_t)r * Ee + s;
    float4 acc = make_float4(0.f, 0.f, 0.f, 0.f);
    for (int base = 0; base < d; base += 128) {
        int m = min(128, d - base);
        if (t < m) sl[t] = lst[base + t];
        __syncthreads();
        int i = 0;
        for (; i + 4 <= m; i += 4) {
            uint2 u0 = ((const uint2*)(xin + (size_t)sl[i + 0] * Hh))[t];
            uint2 u1 = ((const uint2*)(xin + (size_t)sl[i + 1] * Hh))[t];
            uint2 u2 = ((const uint2*)(xin + (size_t)sl[i + 2] * Hh))[t];
            uint2 u3 = ((const uint2*)(xin + (size_t)sl[i + 3] * Hh))[t];
            acc_h4(acc, u0); acc_h4(acc, u1); acc_h4(acc, u2); acc_h4(acc, u3);
        }
        for (; i < m; i++) {
            uint2 u = ((const uint2*)(xin + (size_t)sl[i] * Hh))[t];
            acc_h4(acc, u);
        }
        if (base + 128 < d) __syncthreads();
    }
    pack4_store(g_agg + (size_t)n * AGGW + r * Hh + t * 4, acc);
}

// ---------------- weight transpose + fp16 hi/lo split (tiled, coalesced) ----------------
__global__ void wt_build_k(const float* __restrict__ wl,
                           const float* __restrict__ wr, int HO,
                           __half* __restrict__ outh, __half* __restrict__ outl) {
    __shared__ float tile[32][33];
    int k0 = blockIdx.x * 32;
    int n0 = blockIdx.y * 32;
    int tx = threadIdx.x & 31, ty = threadIdx.x >> 5;
#pragma unroll
    for (int i = 0; i < 4; i++) {
        int k = k0 + ty + i * 8;
        int n = n0 + tx;
        float v = (k < Hh) ? wl[(size_t)k * HO + n] : wr[(size_t)(k - Hh) * HO + n];
        tile[ty + i * 8][tx] = v;
    }
    __syncthreads();
#pragma unroll
    for (int i = 0; i < 4; i++) {
        int n = n0 + ty + i * 8;
        int k = k0 + tx;
        float v = tile[tx][ty + i * 8];
        __half h, l;
        split1h(v, h, l);
        outh[(size_t)n * KS + k] = h;
        outl[(size_t)n * KS + k] = l;
    }
}
__global__ void wt_build_score_k(const float* __restrict__ w1) {
    __shared__ float tile[32][33];
    int k0 = blockIdx.x * 32;
    int n0 = blockIdx.y * 32;
    int tx = threadIdx.x & 31, ty = threadIdx.x >> 5;
#pragma unroll
    for (int i = 0; i < 4; i++) {
        int k = k0 + ty + i * 8;
        tile[ty + i * 8][tx] = w1[(size_t)k * 256 + n0 + tx];
    }
    __syncthreads();
#pragma unroll
    for (int i = 0; i < 4; i++) {
        int n = n0 + ty + i * 8;
        int k = k0 + tx;
        float v = tile[tx][ty + i * 8];
        __half h, l;
        split1h(v, h, l);
        g_wtsh[(size_t)n * 768 + k] = h;
        g_wtsl[(size_t)n * 768 + k] = l;
    }
}

// ---------------- RGCN GEMM (KC=32, 3-stage, 1 sync/chunk) ----------------
// MODE 0: relu + fp16 oh; MODE 1: fp16 oh (no relu); MODE 2: fp32 outf
template <int HO, int MODE>
__global__ void __launch_bounds__(256, 2) rgcn_mma_k(
    const __half* __restrict__ xh,
    const __half* __restrict__ wth, const __half* __restrict__ wtl,
    float* __restrict__ outf,
    __half* __restrict__ oh) {
    extern __shared__ char sm_[];
    const uint32_t sb = smem_u32(sm_);
    const int tid = threadIdx.x;
    const int wid = tid >> 5, lane = tid & 31;
    const int wm = wid & 1, wn = wid >> 1;
    const int m0 = blockIdx.y * MT;
    const int n0 = blockIdx.x * NTT;

    auto load_stage = [&](int c) {
        uint32_t stage = sb + (uint32_t)(c % 3) * STAGE;
        int colA = c * KC;
#pragma unroll
        for (int u = 0; u < 2; u++) {
            int idx = tid * 2 + u;
            int row = idx >> 2, q = idx & 3;
            uint32_t d = stage + (uint32_t)row * 80u + (uint32_t)q * 16u;
            int gr = m0 + row;
            if (gr >= Nn) gr = Nn - 1;
            const __half* ah;
            if (colA < Hh) {
                ah = xh + (size_t)gr * Hh + colA + q * 8;
            } else {
                ah = g_agg + (size_t)gr * AGGW + (colA - Hh) + q * 8;
            }
            CP16(d + A_HI, ah);
            size_t ob = (size_t)(n0 + row) * KS + colA + q * 8;
            CP16(d + B_HI, wth + ob);
            CP16(d + B_LO, wtl + ob);
        }
        CPCOMMIT();
    };

    float acc[4][4][4];
#pragma unroll
    for (int i = 0; i < 4; i++)
#pragma unroll
        for (int j = 0; j < 4; j++)
#pragma unroll
            for (int e = 0; e < 4; e++) acc[i][j][e] = 0.f;

    load_stage(0);
    load_stage(1);

    for (int c = 0; c < CHUNKS; c++) {
        if (c + 1 < CHUNKS) { CPWAIT(1); } else { CPWAIT(0); }
        __syncthreads();
        if (c + 2 < CHUNKS) load_stage(c + 2);
        mma_chunk(sb + (uint32_t)(c % 3) * STAGE, wm, wn, lane, acc);
    }

#pragma unroll
    for (int i = 0; i < 4; i++) {
        int mr = m0 + wm * 64 + i * 16 + (lane >> 2);
#pragma unroll
        for (int j = 0; j < 4; j++) {
            int col = n0 + wn * 32 + j * 8 + (lane & 3) * 2;
#pragma unroll
            for (int hh = 0; hh < 2; hh++) {
                int row = mr + hh * 8;
                if (row >= Nn) continue;
                float v0 = acc[i][j][hh * 2 + 0];
                float v1 = acc[i][j][hh * 2 + 1];
                if (MODE == 0) { v0 = fmaxf(v0, 0.f); v1 = fmaxf(v1, 0.f); }
                if (MODE == 2) {
                    *(float2*)(outf + (size_t)row * HO + col) = make_float2(v0, v1);
                } else {
                    __half2 hp = __floats2half2_rn(v0, v1);
                    *(uint32_t*)(oh + (size_t)row * Hh + col) =
                        *reinterpret_cast<uint32_t*>(&hp);
                }
            }
        }
    }
}

// ---------------- zero output ----------------
__global__ void zero_out_k(float* __restrict__ out) {
    int p = blockIdx.x * blockDim.x + threadIdx.x;
    if (p < Pp) out[p] = 0.f;
}

// ---------------- scoring GEMM (gathered A, cvt in-kernel, 2-stage, fused dot) ----------------
__global__ void __launch_bounds__(256, 2) score_mma_k(const int* __restrict__ pairs,
                                                      const float* __restrict__ b1,
                                                      const float* __restrict__ bng,
                                                      const float* __restrict__ bnb,
                                                      const float* __restrict__ bnm,
                                                      const float* __restrict__ bnv,
                                                      const float* __restrict__ w2,
                                                      float* __restrict__ out) {
    extern __shared__ char sm_[];
    const uint32_t sb = smem_u32(sm_);
    const int tid = threadIdx.x;
    const int wid = tid >> 5, lane = tid & 31;
    const int wm = wid & 1, wn = wid >> 1;
    const int m0 = blockIdx.y * MT;
    const int n0 = blockIdx.x * NTT;

    const int ar = tid >> 1;
    const int ac = tid & 1;
    const int p = m0 + ar;
    const bool aok = p < Pp;
    const int spi = aok ? pairs[p] : 0;
    const int dpi = aok ? pairs[Pp + p] : 0;
    const uint32_t asts = (uint32_t)ar * 80u + (uint32_t)ac * 32u;

    float acc[4][4][4];
#pragma unroll
    for (int i = 0; i < 4; i++)
#pragma unroll
        for (int j = 0; j < 4; j++)
#pragma unroll
            for (int e = 0; e < 4; e++) acc[i][j][e] = 0.f;

    float4 pref[4];
    auto loadA = [&](int c) {
        int k0 = c * KC + ac * 16;
        int seg = k0 >> 8;
        int off = k0 & 255;
        const float4* zs = (const float4*)(g_z + (size_t)spi * Dd + off);
        const float4* zd = (const float4*)(g_z + (size_t)dpi * Dd + off);
#pragma unroll
        for (int j = 0; j < 4; j++) {
            if (!aok) { pref[j] = make_float4(0.f, 0.f, 0.f, 0.f); continue; }
            if (seg == 0) pref[j] = zs[j];
            else if (seg == 1) pref[j] = zd[j];
            else {
                float4 a = zs[j], b = zd[j];
                pref[j] = make_float4(a.x * b.x, a.y * b.y, a.z * b.z, a.w * b.w);
            }
        }
    };
    auto loadB = [&](int c, uint32_t stage) {
#pragma unroll
        for (int it = 0; it < 4; it++) {
            int idx = tid + it * 256;
            int half_ = idx >> 9;
            int r = idx & 511;
            int n = r >> 2, q = r & 3;
            const __half* srcb = half_ ? g_wtsl : g_wtsh;
            uint32_t dst = stage + (half_ ? B_LO : B_HI) + (uint32_t)n * 80u + (uint32_t)q * 16u;
            CP16(dst, srcb + (size_t)(n0 + n) * 768 + c * KC + q * 8);
        }
        CPCOMMIT();
    };

    loadA(0);
    loadB(0, sb);
#pragma unroll
    for (int j = 0; j < 4; j++) cvt_sts(sb + A_HI + asts + j * 8u, pref[j]);
    CPWAIT(0);
    __syncthreads();

    for (int c = 0; c < SCH; c++) {
        const int cn = c + 1;
        const uint32_t cur = sb + (uint32_t)(c & 1) * STAGE;
        const uint32_t nxt = sb + (uint32_t)(cn & 1) * STAGE;
        if (cn < SCH) { loadA(cn); loadB(cn, nxt); }
        mma_chunk(cur, wm, wn, lane, acc);
        if (cn < SCH) {
#pragma unroll
            for (int j = 0; j < 4; j++)
                cvt_sts(nxt + A_HI + asts + j * 8u, pref[j]);
            CPWAIT(0);
        }
        __syncthreads();
    }

    // fused epilogue: h1 = BN(relu(acc + b1)); partial dot with w2; reduce; atomicAdd
    float part[4][2];
#pragma unroll
    for (int i = 0; i < 4; i++) { part[i][0] = 0.f; part[i][1] = 0.f; }

#pragma unroll
    for (int i = 0; i < 4; i++) {
        int mr = m0 + wm * 64 + i * 16 + (lane >> 2);
#pragma unroll
        for (int j = 0; j < 4; j++) {
            int col = n0 + wn * 32 + j * 8 + (lane & 3) * 2;
            float bia0 = b1[col], bia1 = b1[col + 1];
            float s0 = rsqrtf(bnv[col] + 1e-5f) * bng[col];
            float s1 = rsqrtf(bnv[col + 1] + 1e-5f) * bng[col + 1];
            float m0f = bnm[col], m1f = bnm[col + 1];
            float o0 = bnb[col], o1 = bnb[col + 1];
            float w0 = w2[col], w1 = w2[col + 1];
#pragma unroll
            for (int hh = 0; hh < 2; hh++) {
                int row = mr + hh * 8;
                if (row >= Pp) continue;
                float v0 = fmaxf(acc[i][j][hh * 2 + 0] + bia0, 0.f);
                float v1 = fmaxf(acc[i][j][hh * 2 + 1] + bia1, 0.f);
                v0 = (v0 - m0f) * s0 + o0;
                v1 = (v1 - m1f) * s1 + o1;
                part[i][hh] += v0 * w0 + v1 * w1;
            }
        }
    }
#pragma unroll
    for (int i = 0; i < 4; i++)
#pragma unroll
        for (int hh = 0; hh < 2; hh++) {
            float pv = part[i][hh];
            pv += __shfl_xor_sync(0xffffffffu, pv, 1);
            pv += __shfl_xor_sync(0xffffffffu, pv, 2);
            int row = m0 + wm * 64 + i * 16 + (lane >> 2) + hh * 8;
            if ((lane & 3) == 0 && row < Pp) atomicAdd(out + row, pv);
        }
}

// ---------------- final: bias + degree penalties (in-place on out) ----------------
__global__ void final2_k(const int* __restrict__ pairs,
                         const int* __restrict__ degrees,
                         const float* __restrict__ b2,
                         const float* __restrict__ alpha,
                         const float* __restrict__ beta,
                         float* __restrict__ out) {
    int p = blockIdx.x * blockDim.x + threadIdx.x;
    if (p >= Pp) return;
    float sc = out[p] + b2[0];
    int spi = pairs[p], dpi = pairs[Pp + p];
    float sd = fmaxf((float)degrees[spi], 1.f);
    float dd = fmaxf((float)degrees[dpi], 1.f);
    float ra = fmaxf(alpha[0], 0.f), rb = fmaxf(beta[0], 0.f);
    float base = sc - ra * logf(sd) - rb * logf(dd);
    out[p] = base / (sqrtf(sd) * sqrtf(dd) + 1e-8f);
}

// ---------------- fused LayerNorm + ReLU + residual(xb1 fp16) -> xb0 fp16 ----------------
// reads h from fp16 g_hb
__global__ void ln_relu_add_k(const float* __restrict__ lng,
                              const float* __restrict__ lnb) {
    int n = blockIdx.x;
    int t = threadIdx.x;
    const float4 v = h4_to_f4(((const uint2*)(g_hb + (size_t)n * Hh))[t]);
    float s = v.x + v.y + v.z + v.w;
    float ss = v.x * v.x + v.y * v.y + v.z * v.z + v.w * v.w;
#pragma unroll
    for (int o = 16; o; o >>= 1) {
        s += __shfl_xor_sync(0xffffffff, s, o);
        ss += __shfl_xor_sync(0xffffffff, ss, o);
    }
    __shared__ float sm[4], sm2[4];
    if ((t & 31) == 0) { sm[t >> 5] = s; sm2[t >> 5] = ss; }
    __syncthreads();
    s = sm[0] + sm[1] + sm[2] + sm[3];
    ss = sm2[0] + sm2[1] + sm2[2] + sm2[3];
    float mu = s * (1.f / Hh);
    float var = ss * (1.f / Hh) - mu * mu;
    float rstd = rsqrtf(var + 1e-5f);
    float4 g = ((const float4*)lng)[t];
    float4 b = ((const float4*)lnb)[t];
    float4 xv = h4_to_f4(((const uint2*)(g_xb1 + (size_t)n * Hh))[t]);
    xv.x += fmaxf((v.x - mu) * rstd * g.x + b.x, 0.f);
    xv.y += fmaxf((v.y - mu) * rstd * g.y + b.y, 0.f);
    xv.z += fmaxf((v.z - mu) * rstd * g.z + b.z, 0.f);
    xv.w += fmaxf((v.w - mu) * rstd * g.w + b.w, 0.f);
    pack4_store(g_xb0 + (size_t)n * Hh + t * 4, xv);
}

// ---------------- side stream + events (created at static init) ----------------
namespace {
struct HxStreams {
    cudaStream_t s = nullptr;
    cudaEvent_t evRoot, evCSR, evW1, evW2, evW3, evWS;
    HxStreams() {
        cudaStreamCreateWithFlags(&s, cudaStreamNonBlocking);
        cudaEventCreateWithFlags(&evRoot, cudaEventDisableTiming);
        cudaEventCreateWithFlags(&evCSR, cudaEventDisableTiming);
        cudaEventCreateWithFlags(&evW1, cudaEventDisableTiming);
        cudaEventCreateWithFlags(&evW2, cudaEventDisableTiming);
        cudaEventCreateWithFlags(&evW3, cudaEventDisableTiming);
        cudaEventCreateWithFlags(&evWS, cudaEventDisableTiming);
    }
};
HxStreams g_hx;
}

// ---------------- launch ----------------
extern "C" void kernel_launch(void* const* d_in, const int* in_sizes, int n_in,
                              void* d_out, int out_size) {
    const int*   types     = (const int*)d_in[0];
    const int*   src0      = (const int*)d_in[1];
    const int*   dst0      = (const int*)d_in[2];
    const int*   src1      = (const int*)d_in[3];
    const int*   dst1      = (const int*)d_in[4];
    const int*   src2      = (const int*)d_in[5];
    const int*   dst2      = (const int*)d_in[6];
    const int*   pairs     = (const int*)d_in[7];
    const int*   degrees   = (const int*)d_in[8];
    const float* node_emb  = (const float*)d_in[9];
    const float* type_emb  = (const float*)d_in[10];
    const float* w_loop_in  = (const float*)d_in[11];
    const float* w_rel_in   = (const float*)d_in[12];
    const float* w_loop_res = (const float*)d_in[13];
    const float* w_rel_res  = (const float*)d_in[14];
    const float* ln_g       = (const float*)d_in[15];
    const float* ln_b       = (const float*)d_in[16];
    const float* w_loop_out = (const float*)d_in[17];
    const float* w_rel_out  = (const float*)d_in[18];
    const float* lp_w1      = (const float*)d_in[19];
    const float* lp_b1      = (const float*)d_in[20];
    const float* bn_g       = (const float*)d_in[21];
    const float* bn_b       = (const float*)d_in[22];
    const float* bn_mean    = (const float*)d_in[23];
    const float* bn_var     = (const float*)d_in[24];
    const float* lp_w2      = (const float*)d_in[25];
    const float* lp_b2      = (const float*)d_in[26];
    const float* alpha      = (const float*)d_in[27];
    const float* beta       = (const float*)d_in[28];
    float* out = (float*)d_out;

    float *pz;
    __half *pxb0, *pxb1, *phb;
    __half *pw1h, *pw1l, *pw2h, *pw2l, *pw3h, *pw3l;
    cudaGetSymbolAddress((void**)&pz,   g_z);
    cudaGetSymbolAddress((void**)&phb,  g_hb);
    cudaGetSymbolAddress((void**)&pxb0, g_xb0);
    cudaGetSymbolAddress((void**)&pxb1, g_xb1);
    cudaGetSymbolAddress((void**)&pw1h, g_wt1h);
    cudaGetSymbolAddress((void**)&pw1l, g_wt1l);
    cudaGetSymbolAddress((void**)&pw2h, g_wt2h);
    cudaGetSymbolAddress((void**)&pw2l, g_wt2l);
    cudaGetSymbolAddress((void**)&pw3h, g_wt3h);
    cudaGetSymbolAddress((void**)&pw3l, g_wt3l);

    cudaFuncSetAttribute(rgcn_mma_k<512, 0>,
                         cudaFuncAttributeMaxDynamicSharedMemorySize, SMEM_TC3);
    cudaFuncSetAttribute(rgcn_mma_k<512, 1>,
                         cudaFuncAttributeMaxDynamicSharedMemorySize, SMEM_TC3);
    cudaFuncSetAttribute(rgcn_mma_k<256, 2>,
                         cudaFuncAttributeMaxDynamicSharedMemorySize, SMEM_TC3);
    cudaFuncSetAttribute(score_mma_k,
                         cudaFuncAttributeMaxDynamicSharedMemorySize, SMEM_SC);

    const int ENC_BLKS = (Nn * (Hh / 4) + 255) / 256;
    const int E_BLKS   = (Ee + 255) / 256;
    const int Z_BLKS   = (3 * Nn + 255) / 256;
    const int P_BLKS   = (Pp + 255) / 256;
    const dim3 G1(512 / NTT, (Nn + MT - 1) / MT);
    const dim3 G3(256 / NTT, (Nn + MT - 1) / MT);
    const dim3 GSc(256 / NTT, (Pp + MT - 1) / MT);
    const dim3 GAGG(Nn, 3);
    const dim3 GSCAN(SCNB, 3);
    const dim3 GWT512(KS / 32, 512 / 32);
    const dim3 GWT256(KS / 32, 256 / 32);
    const dim3 GWTS(768 / 32, 256 / 32);

    cudaStream_t sw = g_hx.s;

    cudaEventRecord(g_hx.evRoot, 0);
    cudaStreamWaitEvent(sw, g_hx.evRoot, 0);

    // ---- side stream: CSR build, weight splits, output zero ----
    csr_zero_k<<<Z_BLKS, 256, 0, sw>>>();
    csr_count_k<<<E_BLKS, 256, 0, sw>>>(dst0, dst1, dst2);
    csr_scan1_k<<<GSCAN, SCB, 0, sw>>>();
    csr_scan2_k<<<3, SCB, 0, sw>>>();
    csr_scan3_k<<<GSCAN, SCB, 0, sw>>>();
    csr_fill_k<<<E_BLKS, 256, 0, sw>>>(src0, dst0, src1, dst1, src2, dst2);
    cudaEventRecord(g_hx.evCSR, sw);
    wt_build_k<<<GWT512, 256, 0, sw>>>(w_loop_in, w_rel_in, 512, pw1h, pw1l);
    cudaEventRecord(g_hx.evW1, sw);
    wt_build_k<<<GWT512, 256, 0, sw>>>(w_loop_res, w_rel_res, 512, pw2h, pw2l);
    cudaEventRecord(g_hx.evW2, sw);
    wt_build_k<<<GWT256, 256, 0, sw>>>(w_loop_out, w_rel_out, 256, pw3h, pw3l);
    cudaEventRecord(g_hx.evW3, sw);
    wt_build_score_k<<<GWTS, 256, 0, sw>>>(lp_w1);
    zero_out_k<<<P_BLKS, 256, 0, sw>>>(out);
    cudaEventRecord(g_hx.evWS, sw);

    // ---- main stream: critical path ----
    encode_k<<<ENC_BLKS, 256>>>(types, node_emb, type_emb);

    cudaStreamWaitEvent(0, g_hx.evCSR, 0);
    agg_k<<<GAGG, 128>>>(pxb0);
    cudaStreamWaitEvent(0, g_hx.evW1, 0);
    rgcn_mma_k<512, 0><<<G1, 256, SMEM_TC3>>>(pxb0, pw1h, pw1l, nullptr, pxb1);

    agg_k<<<GAGG, 128>>>(pxb1);
    cudaStreamWaitEvent(0, g_hx.evW2, 0);
    rgcn_mma_k<512, 1><<<G1, 256, SMEM_TC3>>>(pxb1, pw2h, pw2l, nullptr, phb);
    ln_relu_add_k<<<Nn, 128>>>(ln_g, ln_b);

    agg_k<<<GAGG, 128>>>(pxb0);
    cudaStreamWaitEvent(0, g_hx.evW3, 0);
    rgcn_mma_k<256, 2><<<G3, 256, SMEM_TC3>>>(pxb0, pw3h, pw3l, pz, nullptr);

    // ---- scoring ----
    cudaStreamWaitEvent(0, g_hx.evWS, 0);
    score_mma_k<<<GSc, 256, SMEM_SC>>>(pairs, lp_b1, bn_g, bn_b, bn_mean, bn_var,
                                       lp_w2, out);
    final2_k<<<P_BLKS, 256>>>(pairs, degrees, lp_b2, alpha, beta, out);
}